// round 1
// baseline (speedup 1.0000x reference)
#include <cuda_runtime.h>
#include <math.h>

#define EMB   512
#define NHEAD 8
#define DHEAD 64
#define SEQ   2048
#define BATCH 4
#define MROWS (BATCH*SEQ)

// Scratch (no cudaMalloc allowed): q, k, v after projection+quantize, and attn output.
__device__ float g_q[MROWS*EMB];
__device__ float g_k[MROWS*EMB];
__device__ float g_v[MROWS*EMB];
__device__ float g_att[MROWS*EMB];

// ---------------------------------------------------------------------------
// C[M,512] = A[M,512] @ W[512,512]^T + bias, optional fake-quantize epilogue.
// 64x64 tile, BK=16, 256 threads, 4x4 micro-tile.
// ---------------------------------------------------------------------------
__global__ __launch_bounds__(256) void gemm_bias_quant(
    const float* __restrict__ A, const float* __restrict__ W,
    const float* __restrict__ bias, float* __restrict__ C,
    const float* __restrict__ bq, const float* __restrict__ eq, int doQuant)
{
    __shared__ float As[16][68];   // As[k][m]
    __shared__ float Bs[16][68];   // Bs[k][n]

    const int tid = threadIdx.x;
    const int tx = tid & 15;       // n micro index
    const int ty = tid >> 4;       // m micro index
    const int m0 = blockIdx.y * 64;
    const int n0 = blockIdx.x * 64;

    const int lrow = tid >> 2;     // 0..63
    const int lseg = tid & 3;      // 0..3 (float4 segment within 16-wide k slab)

    const float* Aptr = A + (size_t)(m0 + lrow) * EMB + lseg * 4;
    const float* Wptr = W + (size_t)(n0 + lrow) * EMB + lseg * 4;

    float acc[4][4] = {};

    for (int kb = 0; kb < EMB; kb += 16) {
        float4 av = *(const float4*)(Aptr + kb);
        float4 bv = *(const float4*)(Wptr + kb);
        As[lseg*4+0][lrow] = av.x; As[lseg*4+1][lrow] = av.y;
        As[lseg*4+2][lrow] = av.z; As[lseg*4+3][lrow] = av.w;
        Bs[lseg*4+0][lrow] = bv.x; Bs[lseg*4+1][lrow] = bv.y;
        Bs[lseg*4+2][lrow] = bv.z; Bs[lseg*4+3][lrow] = bv.w;
        __syncthreads();
        #pragma unroll
        for (int kk = 0; kk < 16; kk++) {
            float4 a = *(const float4*)&As[kk][ty*4];
            float4 b = *(const float4*)&Bs[kk][tx*4];
            acc[0][0] += a.x*b.x; acc[0][1] += a.x*b.y; acc[0][2] += a.x*b.z; acc[0][3] += a.x*b.w;
            acc[1][0] += a.y*b.x; acc[1][1] += a.y*b.y; acc[1][2] += a.y*b.z; acc[1][3] += a.y*b.w;
            acc[2][0] += a.z*b.x; acc[2][1] += a.z*b.y; acc[2][2] += a.z*b.z; acc[2][3] += a.z*b.w;
            acc[3][0] += a.w*b.x; acc[3][1] += a.w*b.y; acc[3][2] += a.w*b.z; acc[3][3] += a.w*b.w;
        }
        __syncthreads();
    }

    // Epilogue: bias (+ optional quantize), float4 stores.
    float qs = 1.f, qinv = 1.f, qlo = 0.f, qhi = 0.f;
    if (doQuant) {
        float b = fminf(fmaxf(*bq, 1.0f), 8.0f);
        float e = *eq;
        qs  = exp2f(e);
        qinv = exp2f(-e);
        float p = exp2f(b - 1.0f);
        qlo = -p;
        qhi = p - 1.0f;
    }
    float4 bcol = *(const float4*)&bias[n0 + tx*4];
    #pragma unroll
    for (int i = 0; i < 4; i++) {
        float r[4];
        #pragma unroll
        for (int j = 0; j < 4; j++) {
            float c = acc[i][j] + ((const float*)&bcol)[j];
            if (doQuant) {
                float t = c * qinv;
                t = fminf(fmaxf(t, qlo), qhi);
                c = floorf(t) * qs;
            }
            r[j] = c;
        }
        *(float4*)&C[(size_t)(m0 + ty*4 + i) * EMB + n0 + tx*4] =
            make_float4(r[0], r[1], r[2], r[3]);
    }
}

// ---------------------------------------------------------------------------
// Flash attention (no mask). One block = one (n, h, 64-query tile).
// q/k/v in [N*T, E] layout with head offset h*64. Online softmax.
// smem: qT[d][r], kT[d][c] (transposed for LDS.128 S-phase),
//       vs[c][dd], ps[r][c] (STS.128 writes, broadcast reads in PV-phase).
// ---------------------------------------------------------------------------
#define FSTR 68
#define FBUF (64*FSTR)

__global__ __launch_bounds__(256) void flash_attn(
    const float* __restrict__ gq, const float* __restrict__ gk,
    const float* __restrict__ gv, float* __restrict__ go)
{
    extern __shared__ float sm[];
    float* qT = sm;
    float* kT = sm + FBUF;
    float* vs = sm + 2*FBUF;
    float* ps = sm + 3*FBUF;

    const int tid = threadIdx.x;
    const int tx = tid & 15;     // col / dcol micro index (16-lane row group)
    const int ty = tid >> 4;     // row micro index
    const int q0 = blockIdx.x * 64;
    const int h  = blockIdx.y;
    const int n  = blockIdx.z;

    const float* qbase  = gq + ((size_t)n*SEQ + q0)*EMB + h*DHEAD;
    const float* kbase0 = gk + (size_t)n*SEQ*EMB + h*DHEAD;
    const float* vbase0 = gv + (size_t)n*SEQ*EMB + h*DHEAD;

    // load q tile transposed: qT[d][r]
    for (int idx = tid; idx < 64*64; idx += 256) {
        int r = idx >> 6, d = idx & 63;
        qT[d*FSTR + r] = qbase[(size_t)r*EMB + d];
    }

    float accO[4][4] = {};
    float mrow[4], lrow[4];
    #pragma unroll
    for (int i = 0; i < 4; i++) { mrow[i] = -1e30f; lrow[i] = 0.0f; }

    const float SM_SCALE = 0.044194173824159216f;  // 1/sqrt(512)

    for (int kb = 0; kb < SEQ; kb += 64) {
        __syncthreads();   // previous PV-phase done before overwriting kT/vs/ps
        const float* kbase = kbase0 + (size_t)kb*EMB;
        const float* vbase = vbase0 + (size_t)kb*EMB;
        for (int idx = tid; idx < 64*64; idx += 256) {
            int c = idx >> 6, d = idx & 63;
            kT[d*FSTR + c] = kbase[(size_t)c*EMB + d];
            vs[c*FSTR + d] = vbase[(size_t)c*EMB + d];
        }
        __syncthreads();

        // ---- S = q @ k^T (rows ty*4.., cols tx*4..) ----
        float s[4][4] = {};
        #pragma unroll 4
        for (int d = 0; d < 64; d++) {
            float4 a = *(const float4*)&qT[d*FSTR + ty*4];
            float4 b = *(const float4*)&kT[d*FSTR + tx*4];
            s[0][0] += a.x*b.x; s[0][1] += a.x*b.y; s[0][2] += a.x*b.z; s[0][3] += a.x*b.w;
            s[1][0] += a.y*b.x; s[1][1] += a.y*b.y; s[1][2] += a.y*b.z; s[1][3] += a.y*b.w;
            s[2][0] += a.z*b.x; s[2][1] += a.z*b.y; s[2][2] += a.z*b.z; s[2][3] += a.z*b.w;
            s[3][0] += a.w*b.x; s[3][1] += a.w*b.y; s[3][2] += a.w*b.z; s[3][3] += a.w*b.w;
        }

        // ---- online softmax per row (16 lanes share a row-group) ----
        #pragma unroll
        for (int i = 0; i < 4; i++) {
            float rmax = -1e30f;
            #pragma unroll
            for (int j = 0; j < 4; j++) { s[i][j] *= SM_SCALE; rmax = fmaxf(rmax, s[i][j]); }
            #pragma unroll
            for (int off = 1; off < 16; off <<= 1)
                rmax = fmaxf(rmax, __shfl_xor_sync(0xffffffffu, rmax, off));
            float mnew  = fmaxf(mrow[i], rmax);
            float alpha = __expf(mrow[i] - mnew);
            float rsum = 0.0f;
            #pragma unroll
            for (int j = 0; j < 4; j++) {
                float p = __expf(s[i][j] - mnew);
                s[i][j] = p; rsum += p;
            }
            #pragma unroll
            for (int off = 1; off < 16; off <<= 1)
                rsum += __shfl_xor_sync(0xffffffffu, rsum, off);
            lrow[i] = lrow[i]*alpha + rsum;
            mrow[i] = mnew;
            #pragma unroll
            for (int j = 0; j < 4; j++) accO[i][j] *= alpha;
            // ps[r][c], contiguous in c -> STS.128
            *(float4*)&ps[(ty*4 + i)*FSTR + tx*4] = make_float4(s[i][0], s[i][1], s[i][2], s[i][3]);
        }
        __syncthreads();

        // ---- O += P @ V (rows ty*4.., dcols tx*4..) ----
        #pragma unroll 4
        for (int c = 0; c < 64; c++) {
            float p0 = ps[(ty*4+0)*FSTR + c];
            float p1 = ps[(ty*4+1)*FSTR + c];
            float p2 = ps[(ty*4+2)*FSTR + c];
            float p3 = ps[(ty*4+3)*FSTR + c];
            float4 v = *(const float4*)&vs[c*FSTR + tx*4];
            accO[0][0] += p0*v.x; accO[0][1] += p0*v.y; accO[0][2] += p0*v.z; accO[0][3] += p0*v.w;
            accO[1][0] += p1*v.x; accO[1][1] += p1*v.y; accO[1][2] += p1*v.z; accO[1][3] += p1*v.w;
            accO[2][0] += p2*v.x; accO[2][1] += p2*v.y; accO[2][2] += p2*v.z; accO[2][3] += p2*v.w;
            accO[3][0] += p3*v.x; accO[3][1] += p3*v.y; accO[3][2] += p3*v.z; accO[3][3] += p3*v.w;
        }
    }

    float* obase = go + ((size_t)n*SEQ + q0)*EMB + h*DHEAD;
    #pragma unroll
    for (int i = 0; i < 4; i++) {
        float inv = 1.0f / lrow[i];
        *(float4*)&obase[(size_t)(ty*4 + i)*EMB + tx*4] =
            make_float4(accO[i][0]*inv, accO[i][1]*inv, accO[i][2]*inv, accO[i][3]*inv);
    }
}

// ---------------------------------------------------------------------------
extern "C" void kernel_launch(void* const* d_in, const int* in_sizes, int n_in,
                              void* d_out, int out_size)
{
    const float* values = (const float*)d_in[0];
    const float* keys   = (const float*)d_in[1];
    const float* query  = (const float*)d_in[2];
    const float* Wq = (const float*)d_in[3];  const float* bq = (const float*)d_in[4];
    const float* Wk = (const float*)d_in[5];  const float* bk = (const float*)d_in[6];
    const float* Wv = (const float*)d_in[7];  const float* bv = (const float*)d_in[8];
    const float* Wo = (const float*)d_in[9];  const float* bo = (const float*)d_in[10];
    const float* bpar = (const float*)d_in[11];
    const float* epar = (const float*)d_in[12];

    float *pq, *pk, *pv, *pa;
    cudaGetSymbolAddress((void**)&pq, g_q);
    cudaGetSymbolAddress((void**)&pk, g_k);
    cudaGetSymbolAddress((void**)&pv, g_v);
    cudaGetSymbolAddress((void**)&pa, g_att);

    dim3 gblk(256);
    dim3 ggrid(EMB/64, MROWS/64);

    gemm_bias_quant<<<ggrid, gblk>>>(query,  Wq, bq, pq, bpar, epar, 1);
    gemm_bias_quant<<<ggrid, gblk>>>(keys,   Wk, bk, pk, bpar, epar, 1);
    gemm_bias_quant<<<ggrid, gblk>>>(values, Wv, bv, pv, bpar, epar, 1);

    const int FSMEM = 4 * FBUF * (int)sizeof(float);  // 69632 bytes
    static int smem_set = 0;
    cudaFuncSetAttribute(flash_attn, cudaFuncAttributeMaxDynamicSharedMemorySize, FSMEM);
    (void)smem_set;
    flash_attn<<<dim3(SEQ/64, NHEAD, BATCH), 256, FSMEM>>>(pq, pk, pv, pa);

    gemm_bias_quant<<<ggrid, gblk>>>(pa, Wo, bo, (float*)d_out, bpar, epar, 0);
}

// round 3
// speedup vs baseline: 1.8350x; 1.8350x over previous
#include <cuda_runtime.h>
#include <cuda_bf16.h>
#include <cstdint>
#include <math.h>

#define EMB   512
#define NHEAD 8
#define DHEAD 64
#define SEQ   2048
#define BATCH 4
#define MROWS (BATCH*SEQ)

// Scratch (no cudaMalloc allowed)
__device__ float g_q[MROWS*EMB];
__device__ float g_k[MROWS*EMB];
__device__ float g_v[MROWS*EMB];
__device__ float g_att[MROWS*EMB];

// ---------------------------------------------------------------------------
// helpers
// ---------------------------------------------------------------------------
__device__ __forceinline__ uint32_t pk_bf16x2(float lo, float hi) {
    uint32_t r;
    asm("cvt.rn.bf16x2.f32 %0, %1, %2;" : "=r"(r) : "f"(hi), "f"(lo));
    return r;
}

// bf16 HMMA m16n8k16, row.col, fp32 accumulate (arch-agnostic: works on compute_103)
__device__ __forceinline__ void mma16816(float* c, const uint32_t* a, uint32_t b0, uint32_t b1) {
    asm volatile(
        "mma.sync.aligned.m16n8k16.row.col.f32.bf16.bf16.f32 "
        "{%0,%1,%2,%3}, {%4,%5,%6,%7}, {%8,%9}, {%0,%1,%2,%3};"
        : "+f"(c[0]), "+f"(c[1]), "+f"(c[2]), "+f"(c[3])
        : "r"(a[0]), "r"(a[1]), "r"(a[2]), "r"(a[3]), "r"(b0), "r"(b1));
}

// all-FMA 2^x (no MUFU). |rel err| < 3e-6 on f in [-0.5,0.5]; valid x >= -80 (clamped).
__device__ __forceinline__ float fexp2(float x) {
    x = fmaxf(x, -80.0f);
    float t = x + 12582912.0f;            // 1.5*2^23 magic: round-to-nearest-int
    float n = t - 12582912.0f;
    float f = x - n;                      // f in [-0.5, 0.5]
    float p = 1.3333558146e-3f;
    p = fmaf(p, f, 9.6181291794e-3f);
    p = fmaf(p, f, 5.5504108664e-2f);
    p = fmaf(p, f, 2.4022650696e-1f);
    p = fmaf(p, f, 6.9314718056e-1f);
    p = fmaf(p, f, 1.0f);
    int ni = __float_as_int(t) - 0x4B400000;   // integer n
    return __int_as_float(__float_as_int(p) + (ni << 23));
}

// ---------------------------------------------------------------------------
// fp32 SIMT GEMM: C[M,512] = A @ W^T + bias, optional quantize epilogue.
// ---------------------------------------------------------------------------
__global__ __launch_bounds__(256) void gemm_bias_quant(
    const float* __restrict__ A, const float* __restrict__ W,
    const float* __restrict__ bias, float* __restrict__ C,
    const float* __restrict__ bq, const float* __restrict__ eq, int doQuant)
{
    __shared__ float As[16][68];
    __shared__ float Bs[16][68];

    const int tid = threadIdx.x;
    const int tx = tid & 15;
    const int ty = tid >> 4;
    const int m0 = blockIdx.y * 64;
    const int n0 = blockIdx.x * 64;
    const int lrow = tid >> 2;
    const int lseg = tid & 3;

    const float* Aptr = A + (size_t)(m0 + lrow) * EMB + lseg * 4;
    const float* Wptr = W + (size_t)(n0 + lrow) * EMB + lseg * 4;

    float acc[4][4] = {};

    for (int kb = 0; kb < EMB; kb += 16) {
        float4 av = *(const float4*)(Aptr + kb);
        float4 bv = *(const float4*)(Wptr + kb);
        As[lseg*4+0][lrow] = av.x; As[lseg*4+1][lrow] = av.y;
        As[lseg*4+2][lrow] = av.z; As[lseg*4+3][lrow] = av.w;
        Bs[lseg*4+0][lrow] = bv.x; Bs[lseg*4+1][lrow] = bv.y;
        Bs[lseg*4+2][lrow] = bv.z; Bs[lseg*4+3][lrow] = bv.w;
        __syncthreads();
        #pragma unroll
        for (int kk = 0; kk < 16; kk++) {
            float4 a = *(const float4*)&As[kk][ty*4];
            float4 b = *(const float4*)&Bs[kk][tx*4];
            acc[0][0] += a.x*b.x; acc[0][1] += a.x*b.y; acc[0][2] += a.x*b.z; acc[0][3] += a.x*b.w;
            acc[1][0] += a.y*b.x; acc[1][1] += a.y*b.y; acc[1][2] += a.y*b.z; acc[1][3] += a.y*b.w;
            acc[2][0] += a.z*b.x; acc[2][1] += a.z*b.y; acc[2][2] += a.z*b.z; acc[2][3] += a.z*b.w;
            acc[3][0] += a.w*b.x; acc[3][1] += a.w*b.y; acc[3][2] += a.w*b.z; acc[3][3] += a.w*b.w;
        }
        __syncthreads();
    }

    float qs = 1.f, qinv = 1.f, qlo = 0.f, qhi = 0.f;
    if (doQuant) {
        float b = fminf(fmaxf(*bq, 1.0f), 8.0f);
        float e = *eq;
        qs  = exp2f(e);  qinv = exp2f(-e);
        float p = exp2f(b - 1.0f);
        qlo = -p;  qhi = p - 1.0f;
    }
    float4 bcol = *(const float4*)&bias[n0 + tx*4];
    #pragma unroll
    for (int i = 0; i < 4; i++) {
        float r[4];
        #pragma unroll
        for (int j = 0; j < 4; j++) {
            float c = acc[i][j] + ((const float*)&bcol)[j];
            if (doQuant) {
                float t = c * qinv;
                t = fminf(fmaxf(t, qlo), qhi);
                c = floorf(t) * qs;
            }
            r[j] = c;
        }
        *(float4*)&C[(size_t)(m0 + ty*4 + i) * EMB + n0 + tx*4] =
            make_float4(r[0], r[1], r[2], r[3]);
    }
}

// ---------------------------------------------------------------------------
// Flash attention on HMMA (mma.sync bf16). 256 threads = 8 warps.
// BQ=128 (warp owns 16 rows), BK=64, D=64.
// Q fragments resident in registers; K row-major smem; V transposed smem.
// S exact in bf16 (quantized ints); P 2-term bf16 split; base-2 softmax, FMA exp.
// ---------------------------------------------------------------------------
#define KSTR 72

__global__ __launch_bounds__(256) void flash_hmma(
    const float* __restrict__ gq, const float* __restrict__ gk,
    const float* __restrict__ gv, float* __restrict__ go)
{
    __shared__ __align__(16) __nv_bfloat16 Ks[64][KSTR];   // [kv][d]
    __shared__ __align__(16) __nv_bfloat16 VTs[64][KSTR];  // [d][kv]

    const int tid  = threadIdx.x;
    const int wid  = tid >> 5;
    const int lane = tid & 31;
    const int g    = lane >> 2;   // row-in-tile group (0..7)
    const int tig  = lane & 3;    // thread-in-group

    const int q0 = blockIdx.x * 128;
    const int h  = blockIdx.y;
    const int n  = blockIdx.z;

    const float* qb  = gq + ((size_t)n*SEQ + q0 + wid*16)*EMB + h*DHEAD;
    const float* kb0 = gk + (size_t)n*SEQ*EMB + h*DHEAD;
    const float* vb0 = gv + (size_t)n*SEQ*EMB + h*DHEAD;

    // ---- Q fragments (16 x 64 per warp), resident in regs. Exact bf16. ----
    uint32_t qa[4][4];
    {
        const float* r0 = qb + (size_t)g*EMB;
        const float* r1 = qb + (size_t)(g+8)*EMB;
        #pragma unroll
        for (int u = 0; u < 4; u++) {
            int d0 = tig*2 + 16*u;
            float2 v00 = *(const float2*)(r0 + d0);
            float2 v10 = *(const float2*)(r1 + d0);
            float2 v01 = *(const float2*)(r0 + d0 + 8);
            float2 v11 = *(const float2*)(r1 + d0 + 8);
            qa[u][0] = pk_bf16x2(v00.x, v00.y);
            qa[u][1] = pk_bf16x2(v10.x, v10.y);
            qa[u][2] = pk_bf16x2(v01.x, v01.y);
            qa[u][3] = pk_bf16x2(v11.x, v11.y);
        }
    }

    float o[8][4];
    #pragma unroll
    for (int j = 0; j < 8; j++) { o[j][0]=0.f; o[j][1]=0.f; o[j][2]=0.f; o[j][3]=0.f; }
    float m0 = -1e30f, m1 = -1e30f, l0 = 0.f, l1 = 0.f;

    const float C = 0.06375892f;  // log2(e)/sqrt(512)

    for (int t = 0; t < SEQ/64; t++) {
        // ---- stage K (row-major) and V (transposed) tiles as bf16 ----
        const float* kb = kb0 + (size_t)(t*64)*EMB;
        const float* vb = vb0 + (size_t)(t*64)*EMB;
        #pragma unroll
        for (int it = 0; it < 8; it++) {
            int idx = tid + it*256;
            int kv = idx >> 5, dp = idx & 31;
            float2 kv2 = *(const float2*)(kb + (size_t)kv*EMB + dp*2);
            *(uint32_t*)&Ks[kv][dp*2] = pk_bf16x2(kv2.x, kv2.y);
            float2 vv2 = *(const float2*)(vb + (size_t)kv*EMB + dp*2);
            VTs[dp*2  ][kv] = __float2bfloat16(vv2.x);
            VTs[dp*2+1][kv] = __float2bfloat16(vv2.y);
        }
        __syncthreads();

        // ---- S = Q @ K^T  (warp tile [16 x 64]) ----
        float sacc[8][4];
        #pragma unroll
        for (int j = 0; j < 8; j++) { sacc[j][0]=0.f; sacc[j][1]=0.f; sacc[j][2]=0.f; sacc[j][3]=0.f; }
        #pragma unroll
        for (int u = 0; u < 4; u++) {
            #pragma unroll
            for (int j = 0; j < 8; j++) {
                uint32_t b0 = *(const uint32_t*)&Ks[g + 8*j][tig*2 + 16*u];
                uint32_t b1 = *(const uint32_t*)&Ks[g + 8*j][tig*2 + 8 + 16*u];
                mma16816(sacc[j], qa[u], b0, b1);
            }
        }

        // ---- online softmax (rows g and g+8 of this warp's 16) ----
        float rm0 = -1e30f, rm1 = -1e30f;
        #pragma unroll
        for (int j = 0; j < 8; j++) {
            rm0 = fmaxf(rm0, fmaxf(sacc[j][0], sacc[j][1]));
            rm1 = fmaxf(rm1, fmaxf(sacc[j][2], sacc[j][3]));
        }
        rm0 = fmaxf(rm0, __shfl_xor_sync(0xffffffffu, rm0, 1));
        rm0 = fmaxf(rm0, __shfl_xor_sync(0xffffffffu, rm0, 2));
        rm1 = fmaxf(rm1, __shfl_xor_sync(0xffffffffu, rm1, 1));
        rm1 = fmaxf(rm1, __shfl_xor_sync(0xffffffffu, rm1, 2));

        float mn0 = fmaxf(m0, rm0), mn1 = fmaxf(m1, rm1);
        float a0 = fexp2((m0 - mn0) * C);
        float a1 = fexp2((m1 - mn1) * C);
        m0 = mn0; m1 = mn1;
        l0 *= a0;  l1 *= a1;
        float mc0 = mn0 * C, mc1 = mn1 * C;

        uint32_t phA[8], phB[8], plA[8], plB[8];
        #pragma unroll
        for (int j = 0; j < 8; j++) {
            float p0 = fexp2(fmaf(sacc[j][0], C, -mc0));
            float p1 = fexp2(fmaf(sacc[j][1], C, -mc0));
            float p2 = fexp2(fmaf(sacc[j][2], C, -mc1));
            float p3 = fexp2(fmaf(sacc[j][3], C, -mc1));
            l0 += p0 + p1;  l1 += p2 + p3;
            uint32_t h0 = __float_as_uint(p0) & 0xFFFF0000u;
            uint32_t h1 = __float_as_uint(p1) & 0xFFFF0000u;
            uint32_t h2 = __float_as_uint(p2) & 0xFFFF0000u;
            uint32_t h3 = __float_as_uint(p3) & 0xFFFF0000u;
            phA[j] = h1 | (h0 >> 16);
            phB[j] = h3 | (h2 >> 16);
            plA[j] = pk_bf16x2(p0 - __uint_as_float(h0), p1 - __uint_as_float(h1));
            plB[j] = pk_bf16x2(p2 - __uint_as_float(h2), p3 - __uint_as_float(h3));
            o[j][0] *= a0; o[j][1] *= a0; o[j][2] *= a1; o[j][3] *= a1;
        }

        // ---- O += P @ V  (A = P fragments in regs, B = VT smem) ----
        #pragma unroll
        for (int u = 0; u < 4; u++) {
            uint32_t ah[4] = { phA[2*u], phB[2*u], phA[2*u+1], phB[2*u+1] };
            uint32_t al[4] = { plA[2*u], plB[2*u], plA[2*u+1], plB[2*u+1] };
            #pragma unroll
            for (int j = 0; j < 8; j++) {
                uint32_t b0 = *(const uint32_t*)&VTs[g + 8*j][tig*2 + 16*u];
                uint32_t b1 = *(const uint32_t*)&VTs[g + 8*j][tig*2 + 8 + 16*u];
                mma16816(o[j], ah, b0, b1);
                mma16816(o[j], al, b0, b1);
            }
        }
        __syncthreads();
    }

    // ---- epilogue ----
    l0 += __shfl_xor_sync(0xffffffffu, l0, 1);
    l0 += __shfl_xor_sync(0xffffffffu, l0, 2);
    l1 += __shfl_xor_sync(0xffffffffu, l1, 1);
    l1 += __shfl_xor_sync(0xffffffffu, l1, 2);
    float i0 = 1.0f / l0, i1 = 1.0f / l1;

    float* ob = go + ((size_t)n*SEQ + q0 + wid*16)*EMB + h*DHEAD;
    #pragma unroll
    for (int j = 0; j < 8; j++) {
        *(float2*)(ob + (size_t)g*EMB + 8*j + tig*2)     = make_float2(o[j][0]*i0, o[j][1]*i0);
        *(float2*)(ob + (size_t)(g+8)*EMB + 8*j + tig*2) = make_float2(o[j][2]*i1, o[j][3]*i1);
    }
}

// ---------------------------------------------------------------------------
extern "C" void kernel_launch(void* const* d_in, const int* in_sizes, int n_in,
                              void* d_out, int out_size)
{
    const float* values = (const float*)d_in[0];
    const float* keys   = (const float*)d_in[1];
    const float* query  = (const float*)d_in[2];
    const float* Wq = (const float*)d_in[3];  const float* bq = (const float*)d_in[4];
    const float* Wk = (const float*)d_in[5];  const float* bk = (const float*)d_in[6];
    const float* Wv = (const float*)d_in[7];  const float* bv = (const float*)d_in[8];
    const float* Wo = (const float*)d_in[9];  const float* bo = (const float*)d_in[10];
    const float* bpar = (const float*)d_in[11];
    const float* epar = (const float*)d_in[12];

    float *pq, *pk, *pv, *pa;
    cudaGetSymbolAddress((void**)&pq, g_q);
    cudaGetSymbolAddress((void**)&pk, g_k);
    cudaGetSymbolAddress((void**)&pv, g_v);
    cudaGetSymbolAddress((void**)&pa, g_att);

    dim3 gblk(256);
    dim3 ggrid(EMB/64, MROWS/64);

    gemm_bias_quant<<<ggrid, gblk>>>(query,  Wq, bq, pq, bpar, epar, 1);
    gemm_bias_quant<<<ggrid, gblk>>>(keys,   Wk, bk, pk, bpar, epar, 1);
    gemm_bias_quant<<<ggrid, gblk>>>(values, Wv, bv, pv, bpar, epar, 1);

    flash_hmma<<<dim3(SEQ/128, NHEAD, BATCH), 256>>>(pq, pk, pv, pa);

    gemm_bias_quant<<<ggrid, gblk>>>(pa, Wo, bo, (float*)d_out, bpar, epar, 0);
}

// round 4
// speedup vs baseline: 2.4280x; 1.3232x over previous
#include <cuda_runtime.h>
#include <cuda_bf16.h>
#include <cstdint>
#include <math.h>

#define EMB   512
#define NHEAD 8
#define DHEAD 64
#define SEQ   2048
#define BATCH 4
#define MROWS (BATCH*SEQ)

// Scratch (no cudaMalloc allowed)
__device__ float g_q[MROWS*EMB];
__device__ float g_k[MROWS*EMB];
__device__ float g_v[MROWS*EMB];
__device__ float g_att[MROWS*EMB];

// ---------------------------------------------------------------------------
// helpers
// ---------------------------------------------------------------------------
__device__ __forceinline__ uint32_t pk_bf16x2(float lo, float hi) {
    uint32_t r;
    asm("cvt.rn.bf16x2.f32 %0, %1, %2;" : "=r"(r) : "f"(hi), "f"(lo));
    return r;
}

// truncate-split: a = hi + lo with hi = trunc-bf16(a); packs pairs.
__device__ __forceinline__ void split2(float a, float b, uint32_t& hi, uint32_t& lo) {
    uint32_t ha = __float_as_uint(a) & 0xFFFF0000u;
    uint32_t hb = __float_as_uint(b) & 0xFFFF0000u;
    hi = hb | (ha >> 16);
    lo = pk_bf16x2(a - __uint_as_float(ha), b - __uint_as_float(hb));
}

// bf16 HMMA m16n8k16, row.col, fp32 accumulate (arch-agnostic)
__device__ __forceinline__ void mma16816(float* c, const uint32_t* a, uint32_t b0, uint32_t b1) {
    asm volatile(
        "mma.sync.aligned.m16n8k16.row.col.f32.bf16.bf16.f32 "
        "{%0,%1,%2,%3}, {%4,%5,%6,%7}, {%8,%9}, {%0,%1,%2,%3};"
        : "+f"(c[0]), "+f"(c[1]), "+f"(c[2]), "+f"(c[3])
        : "r"(a[0]), "r"(a[1]), "r"(a[2]), "r"(a[3]), "r"(b0), "r"(b1));
}

// all-FMA 2^x (no MUFU). |rel err| < 3e-6; valid x >= -80 (clamped).
__device__ __forceinline__ float fexp2(float x) {
    x = fmaxf(x, -80.0f);
    float t = x + 12582912.0f;
    float n = t - 12582912.0f;
    float f = x - n;
    float p = 1.3333558146e-3f;
    p = fmaf(p, f, 9.6181291794e-3f);
    p = fmaf(p, f, 5.5504108664e-2f);
    p = fmaf(p, f, 2.4022650696e-1f);
    p = fmaf(p, f, 6.9314718056e-1f);
    p = fmaf(p, f, 1.0f);
    int ni = __float_as_int(t) - 0x4B400000;
    return __int_as_float(__float_as_int(p) + (ni << 23));
}

// ---------------------------------------------------------------------------
// HMMA GEMM with 2-term bf16 split (3 products): C = A @ W^T + bias.
// Tile 128(M) x 64(N), BK=32, 256 threads / 8 warps; warp = 16 rows x 64 cols.
// ---------------------------------------------------------------------------
#define GSTR 40   // bf16 row stride (80B): conflict-free for frag loads

__global__ __launch_bounds__(256, 2) void gemm_hmma(
    const float* __restrict__ A, const float* __restrict__ W,
    const float* __restrict__ bias, float* __restrict__ C,
    const float* __restrict__ bqp, const float* __restrict__ eqp, int doQuant)
{
    __shared__ __align__(16) __nv_bfloat16 Ah[128][GSTR];
    __shared__ __align__(16) __nv_bfloat16 Al[128][GSTR];
    __shared__ __align__(16) __nv_bfloat16 Wh[64][GSTR];
    __shared__ __align__(16) __nv_bfloat16 Wl[64][GSTR];

    const int tid  = threadIdx.x;
    const int wid  = tid >> 5;
    const int lane = tid & 31;
    const int g    = lane >> 2;
    const int tig  = lane & 3;
    const int m0 = blockIdx.y * 128;
    const int n0 = blockIdx.x * 64;

    const int arow = tid >> 1,  ac0 = (tid & 1) * 16;   // A: 128 rows x 32 k
    const int wrow = tid >> 2,  wc0 = (tid & 3) * 8;    // W: 64 rows x 32 k

    float o[8][4] = {};

    for (int kb = 0; kb < EMB; kb += 32) {
        // ---- stage A tile (fp32 -> hi/lo bf16) ----
        const float* ap = A + (size_t)(m0 + arow) * EMB + kb + ac0;
        #pragma unroll
        for (int i = 0; i < 2; i++) {
            float4 v = *(const float4*)(ap + i*8);
            float4 w = *(const float4*)(ap + i*8 + 4);
            uint32_t h0,l0,h1,l1,h2,l2,h3,l3;
            split2(v.x, v.y, h0, l0); split2(v.z, v.w, h1, l1);
            split2(w.x, w.y, h2, l2); split2(w.z, w.w, h3, l3);
            int c = ac0 + i*8;
            *(uint32_t*)&Ah[arow][c+0] = h0; *(uint32_t*)&Ah[arow][c+2] = h1;
            *(uint32_t*)&Ah[arow][c+4] = h2; *(uint32_t*)&Ah[arow][c+6] = h3;
            *(uint32_t*)&Al[arow][c+0] = l0; *(uint32_t*)&Al[arow][c+2] = l1;
            *(uint32_t*)&Al[arow][c+4] = l2; *(uint32_t*)&Al[arow][c+6] = l3;
        }
        // ---- stage W tile ----
        {
            const float* wp = W + (size_t)(n0 + wrow) * EMB + kb + wc0;
            float4 v = *(const float4*)(wp);
            float4 w = *(const float4*)(wp + 4);
            uint32_t h0,l0,h1,l1,h2,l2,h3,l3;
            split2(v.x, v.y, h0, l0); split2(v.z, v.w, h1, l1);
            split2(w.x, w.y, h2, l2); split2(w.z, w.w, h3, l3);
            *(uint32_t*)&Wh[wrow][wc0+0] = h0; *(uint32_t*)&Wh[wrow][wc0+2] = h1;
            *(uint32_t*)&Wh[wrow][wc0+4] = h2; *(uint32_t*)&Wh[wrow][wc0+6] = h3;
            *(uint32_t*)&Wl[wrow][wc0+0] = l0; *(uint32_t*)&Wl[wrow][wc0+2] = l1;
            *(uint32_t*)&Wl[wrow][wc0+4] = l2; *(uint32_t*)&Wl[wrow][wc0+6] = l3;
        }
        __syncthreads();

        // ---- compute: 2 k16 steps, 8 n-tiles, 3 split products ----
        #pragma unroll
        for (int u = 0; u < 2; u++) {
            const int r0 = wid*16 + g, r1 = r0 + 8, kk = u*16 + tig*2;
            uint32_t ah[4], al[4];
            ah[0] = *(const uint32_t*)&Ah[r0][kk];
            ah[1] = *(const uint32_t*)&Ah[r1][kk];
            ah[2] = *(const uint32_t*)&Ah[r0][kk+8];
            ah[3] = *(const uint32_t*)&Ah[r1][kk+8];
            al[0] = *(const uint32_t*)&Al[r0][kk];
            al[1] = *(const uint32_t*)&Al[r1][kk];
            al[2] = *(const uint32_t*)&Al[r0][kk+8];
            al[3] = *(const uint32_t*)&Al[r1][kk+8];
            #pragma unroll
            for (int j = 0; j < 8; j++) {
                uint32_t bh0 = *(const uint32_t*)&Wh[8*j+g][kk];
                uint32_t bh1 = *(const uint32_t*)&Wh[8*j+g][kk+8];
                uint32_t bl0 = *(const uint32_t*)&Wl[8*j+g][kk];
                uint32_t bl1 = *(const uint32_t*)&Wl[8*j+g][kk+8];
                mma16816(o[j], ah, bh0, bh1);
                mma16816(o[j], al, bh0, bh1);
                mma16816(o[j], ah, bl0, bl1);
            }
        }
        __syncthreads();
    }

    // ---- epilogue: bias (+ quantize) ----
    float qs = 1.f, qinv = 1.f, qlo = 0.f, qhi = 0.f;
    if (doQuant) {
        float b = fminf(fmaxf(*bqp, 1.0f), 8.0f);
        float e = *eqp;
        qs = exp2f(e); qinv = exp2f(-e);
        float p = exp2f(b - 1.0f);
        qlo = -p; qhi = p - 1.0f;
    }
    const int mr0 = m0 + wid*16 + g, mr1 = mr0 + 8;
    #pragma unroll
    for (int j = 0; j < 8; j++) {
        int nn = n0 + 8*j + tig*2;
        float b0 = bias[nn], b1 = bias[nn+1];
        float r[4] = { o[j][0]+b0, o[j][1]+b1, o[j][2]+b0, o[j][3]+b1 };
        if (doQuant) {
            #pragma unroll
            for (int q = 0; q < 4; q++) {
                float t = r[q] * qinv;
                t = fminf(fmaxf(t, qlo), qhi);
                r[q] = floorf(t) * qs;
            }
        }
        *(float2*)&C[(size_t)mr0 * EMB + nn] = make_float2(r[0], r[1]);
        *(float2*)&C[(size_t)mr1 * EMB + nn] = make_float2(r[2], r[3]);
    }
}

// ---------------------------------------------------------------------------
// Flash attention on HMMA. 128 threads = 4 warps. BQ=64 (warp = 16 rows), BK=64.
// ---------------------------------------------------------------------------
#define KSTR 72

__global__ __launch_bounds__(128, 3) void flash_hmma(
    const float* __restrict__ gq, const float* __restrict__ gk,
    const float* __restrict__ gv, float* __restrict__ go)
{
    __shared__ __align__(16) __nv_bfloat16 Ks[64][KSTR];   // [kv][d]
    __shared__ __align__(16) __nv_bfloat16 VTs[64][KSTR];  // [d][kv]

    const int tid  = threadIdx.x;
    const int wid  = tid >> 5;
    const int lane = tid & 31;
    const int g    = lane >> 2;
    const int tig  = lane & 3;

    const int q0 = blockIdx.x * 64;
    const int h  = blockIdx.y;
    const int n  = blockIdx.z;

    const float* qb  = gq + ((size_t)n*SEQ + q0 + wid*16)*EMB + h*DHEAD;
    const float* kb0 = gk + (size_t)n*SEQ*EMB + h*DHEAD;
    const float* vb0 = gv + (size_t)n*SEQ*EMB + h*DHEAD;

    // Q fragments resident in regs (exact bf16: quantized ints)
    uint32_t qa[4][4];
    {
        const float* r0 = qb + (size_t)g*EMB;
        const float* r1 = qb + (size_t)(g+8)*EMB;
        #pragma unroll
        for (int u = 0; u < 4; u++) {
            int d0 = tig*2 + 16*u;
            float2 v00 = *(const float2*)(r0 + d0);
            float2 v10 = *(const float2*)(r1 + d0);
            float2 v01 = *(const float2*)(r0 + d0 + 8);
            float2 v11 = *(const float2*)(r1 + d0 + 8);
            qa[u][0] = pk_bf16x2(v00.x, v00.y);
            qa[u][1] = pk_bf16x2(v10.x, v10.y);
            qa[u][2] = pk_bf16x2(v01.x, v01.y);
            qa[u][3] = pk_bf16x2(v11.x, v11.y);
        }
    }

    float o[8][4];
    #pragma unroll
    for (int j = 0; j < 8; j++) { o[j][0]=0.f; o[j][1]=0.f; o[j][2]=0.f; o[j][3]=0.f; }
    float m0 = -1e30f, m1 = -1e30f, l0 = 0.f, l1 = 0.f;

    const float C = 0.06375892f;  // log2(e)/sqrt(512)

    for (int t = 0; t < SEQ/64; t++) {
        const float* kb = kb0 + (size_t)(t*64)*EMB;
        const float* vb = vb0 + (size_t)(t*64)*EMB;
        #pragma unroll
        for (int it = 0; it < 16; it++) {
            int idx = tid + it*128;
            int kv = idx >> 5, dp = idx & 31;
            float2 kv2 = *(const float2*)(kb + (size_t)kv*EMB + dp*2);
            *(uint32_t*)&Ks[kv][dp*2] = pk_bf16x2(kv2.x, kv2.y);
            float2 vv2 = *(const float2*)(vb + (size_t)kv*EMB + dp*2);
            VTs[dp*2  ][kv] = __float2bfloat16(vv2.x);
            VTs[dp*2+1][kv] = __float2bfloat16(vv2.y);
        }
        __syncthreads();

        // ---- S = Q @ K^T ----
        float sacc[8][4];
        #pragma unroll
        for (int j = 0; j < 8; j++) { sacc[j][0]=0.f; sacc[j][1]=0.f; sacc[j][2]=0.f; sacc[j][3]=0.f; }
        #pragma unroll
        for (int u = 0; u < 4; u++) {
            #pragma unroll
            for (int j = 0; j < 8; j++) {
                uint32_t b0 = *(const uint32_t*)&Ks[g + 8*j][tig*2 + 16*u];
                uint32_t b1 = *(const uint32_t*)&Ks[g + 8*j][tig*2 + 8 + 16*u];
                mma16816(sacc[j], qa[u], b0, b1);
            }
        }

        // ---- online softmax ----
        float rm0 = -1e30f, rm1 = -1e30f;
        #pragma unroll
        for (int j = 0; j < 8; j++) {
            rm0 = fmaxf(rm0, fmaxf(sacc[j][0], sacc[j][1]));
            rm1 = fmaxf(rm1, fmaxf(sacc[j][2], sacc[j][3]));
        }
        rm0 = fmaxf(rm0, __shfl_xor_sync(0xffffffffu, rm0, 1));
        rm0 = fmaxf(rm0, __shfl_xor_sync(0xffffffffu, rm0, 2));
        rm1 = fmaxf(rm1, __shfl_xor_sync(0xffffffffu, rm1, 1));
        rm1 = fmaxf(rm1, __shfl_xor_sync(0xffffffffu, rm1, 2));

        float mn0 = fmaxf(m0, rm0), mn1 = fmaxf(m1, rm1);
        float a0 = fexp2((m0 - mn0) * C);
        float a1 = fexp2((m1 - mn1) * C);
        m0 = mn0; m1 = mn1;
        l0 *= a0;  l1 *= a1;
        float mc0 = mn0 * C, mc1 = mn1 * C;

        uint32_t phA[8], phB[8], plA[8], plB[8];
        #pragma unroll
        for (int j = 0; j < 8; j++) {
            float p0 = fexp2(fmaf(sacc[j][0], C, -mc0));
            float p1 = fexp2(fmaf(sacc[j][1], C, -mc0));
            float p2 = fexp2(fmaf(sacc[j][2], C, -mc1));
            float p3 = fexp2(fmaf(sacc[j][3], C, -mc1));
            l0 += p0 + p1;  l1 += p2 + p3;
            uint32_t h0 = __float_as_uint(p0) & 0xFFFF0000u;
            uint32_t h1 = __float_as_uint(p1) & 0xFFFF0000u;
            uint32_t h2 = __float_as_uint(p2) & 0xFFFF0000u;
            uint32_t h3 = __float_as_uint(p3) & 0xFFFF0000u;
            phA[j] = h1 | (h0 >> 16);
            phB[j] = h3 | (h2 >> 16);
            plA[j] = pk_bf16x2(p0 - __uint_as_float(h0), p1 - __uint_as_float(h1));
            plB[j] = pk_bf16x2(p2 - __uint_as_float(h2), p3 - __uint_as_float(h3));
            o[j][0] *= a0; o[j][1] *= a0; o[j][2] *= a1; o[j][3] *= a1;
        }

        // ---- O += P @ V ----
        #pragma unroll
        for (int u = 0; u < 4; u++) {
            uint32_t ah[4] = { phA[2*u], phB[2*u], phA[2*u+1], phB[2*u+1] };
            uint32_t al[4] = { plA[2*u], plB[2*u], plA[2*u+1], plB[2*u+1] };
            #pragma unroll
            for (int j = 0; j < 8; j++) {
                uint32_t b0 = *(const uint32_t*)&VTs[g + 8*j][tig*2 + 16*u];
                uint32_t b1 = *(const uint32_t*)&VTs[g + 8*j][tig*2 + 8 + 16*u];
                mma16816(o[j], ah, b0, b1);
                mma16816(o[j], al, b0, b1);
            }
        }
        __syncthreads();
    }

    // ---- epilogue ----
    l0 += __shfl_xor_sync(0xffffffffu, l0, 1);
    l0 += __shfl_xor_sync(0xffffffffu, l0, 2);
    l1 += __shfl_xor_sync(0xffffffffu, l1, 1);
    l1 += __shfl_xor_sync(0xffffffffu, l1, 2);
    float i0 = 1.0f / l0, i1 = 1.0f / l1;

    float* ob = go + ((size_t)n*SEQ + q0 + wid*16)*EMB + h*DHEAD;
    #pragma unroll
    for (int j = 0; j < 8; j++) {
        *(float2*)(ob + (size_t)g*EMB + 8*j + tig*2)     = make_float2(o[j][0]*i0, o[j][1]*i0);
        *(float2*)(ob + (size_t)(g+8)*EMB + 8*j + tig*2) = make_float2(o[j][2]*i1, o[j][3]*i1);
    }
}

// ---------------------------------------------------------------------------
extern "C" void kernel_launch(void* const* d_in, const int* in_sizes, int n_in,
                              void* d_out, int out_size)
{
    const float* values = (const float*)d_in[0];
    const float* keys   = (const float*)d_in[1];
    const float* query  = (const float*)d_in[2];
    const float* Wq = (const float*)d_in[3];  const float* bq = (const float*)d_in[4];
    const float* Wk = (const float*)d_in[5];  const float* bk = (const float*)d_in[6];
    const float* Wv = (const float*)d_in[7];  const float* bv = (const float*)d_in[8];
    const float* Wo = (const float*)d_in[9];  const float* bo = (const float*)d_in[10];
    const float* bpar = (const float*)d_in[11];
    const float* epar = (const float*)d_in[12];

    float *pq, *pk, *pv, *pa;
    cudaGetSymbolAddress((void**)&pq, g_q);
    cudaGetSymbolAddress((void**)&pk, g_k);
    cudaGetSymbolAddress((void**)&pv, g_v);
    cudaGetSymbolAddress((void**)&pa, g_att);

    dim3 gblk(256);
    dim3 ggrid(EMB/64, MROWS/128);

    gemm_hmma<<<ggrid, gblk>>>(query,  Wq, bq, pq, bpar, epar, 1);
    gemm_hmma<<<ggrid, gblk>>>(keys,   Wk, bk, pk, bpar, epar, 1);
    gemm_hmma<<<ggrid, gblk>>>(values, Wv, bv, pv, bpar, epar, 1);

    flash_hmma<<<dim3(SEQ/64, NHEAD, BATCH), 128>>>(pq, pk, pv, pa);

    gemm_hmma<<<ggrid, gblk>>>(pa, Wo, bo, (float*)d_out, bpar, epar, 0);
}

// round 5
// speedup vs baseline: 3.2518x; 1.3393x over previous
#include <cuda_runtime.h>
#include <cuda_bf16.h>
#include <cstdint>
#include <math.h>

#define EMB   512
#define NHEAD 8
#define DHEAD 64
#define SEQ   2048
#define BATCH 4
#define MROWS (BATCH*SEQ)

// Scratch (no cudaMalloc allowed). q/k/v hold quantized ints -> bf16-exact.
__device__ __nv_bfloat16 g_q[MROWS*EMB];
__device__ __nv_bfloat16 g_k[MROWS*EMB];
__device__ __nv_bfloat16 g_v[MROWS*EMB];
__device__ float         g_att[MROWS*EMB];

// ---------------------------------------------------------------------------
// helpers
// ---------------------------------------------------------------------------
__device__ __forceinline__ uint32_t pk_bf16x2(float lo, float hi) {
    uint32_t r;
    asm("cvt.rn.bf16x2.f32 %0, %1, %2;" : "=r"(r) : "f"(hi), "f"(lo));
    return r;
}

__device__ __forceinline__ void split2(float a, float b, uint32_t& hi, uint32_t& lo) {
    uint32_t ha = __float_as_uint(a) & 0xFFFF0000u;
    uint32_t hb = __float_as_uint(b) & 0xFFFF0000u;
    hi = hb | (ha >> 16);
    lo = pk_bf16x2(a - __uint_as_float(ha), b - __uint_as_float(hb));
}

__device__ __forceinline__ void mma16816(float* c, const uint32_t* a, uint32_t b0, uint32_t b1) {
    asm volatile(
        "mma.sync.aligned.m16n8k16.row.col.f32.bf16.bf16.f32 "
        "{%0,%1,%2,%3}, {%4,%5,%6,%7}, {%8,%9}, {%0,%1,%2,%3};"
        : "+f"(c[0]), "+f"(c[1]), "+f"(c[2]), "+f"(c[3])
        : "r"(a[0]), "r"(a[1]), "r"(a[2]), "r"(a[3]), "r"(b0), "r"(b1));
}

__device__ __forceinline__ void ldm4(uint32_t& r0, uint32_t& r1, uint32_t& r2, uint32_t& r3, uint32_t a) {
    asm volatile("ldmatrix.sync.aligned.m8n8.x4.shared.b16 {%0,%1,%2,%3}, [%4];"
        : "=r"(r0), "=r"(r1), "=r"(r2), "=r"(r3) : "r"(a));
}
__device__ __forceinline__ void ldm4t(uint32_t& r0, uint32_t& r1, uint32_t& r2, uint32_t& r3, uint32_t a) {
    asm volatile("ldmatrix.sync.aligned.m8n8.x4.trans.shared.b16 {%0,%1,%2,%3}, [%4];"
        : "=r"(r0), "=r"(r1), "=r"(r2), "=r"(r3) : "r"(a));
}

__device__ __forceinline__ void cp16(uint32_t dst, const void* src) {
    asm volatile("cp.async.ca.shared.global [%0], [%1], 16;" :: "r"(dst), "l"(src));
}
__device__ __forceinline__ uint32_t smem_u32(const void* p) {
    uint32_t a;
    asm("{ .reg .u64 t; cvta.to.shared.u64 t, %1; cvt.u32.u64 %0, t; }" : "=r"(a) : "l"(p));
    return a;
}

// all-FMA 2^x (no MUFU). |rel err| < 3e-6; valid x >= -80 (clamped).
__device__ __forceinline__ float fexp2(float x) {
    x = fmaxf(x, -80.0f);
    float t = x + 12582912.0f;
    float n = t - 12582912.0f;
    float f = x - n;
    float p = 1.3333558146e-3f;
    p = fmaf(p, f, 9.6181291794e-3f);
    p = fmaf(p, f, 5.5504108664e-2f);
    p = fmaf(p, f, 2.4022650696e-1f);
    p = fmaf(p, f, 6.9314718056e-1f);
    p = fmaf(p, f, 1.0f);
    int ni = __float_as_int(t) - 0x4B400000;
    return __int_as_float(__float_as_int(p) + (ni << 23));
}

// ---------------------------------------------------------------------------
// HMMA GEMM with 2-term bf16 split (3 products): C = A @ W^T + bias.
// QUANT: quantize epilogue + bf16 output (exact ints). else fp32 output.
// ---------------------------------------------------------------------------
#define GSTR 40

template<bool QUANT>
__global__ __launch_bounds__(256, 2) void gemm_hmma(
    const float* __restrict__ A, const float* __restrict__ W,
    const float* __restrict__ bias, void* __restrict__ Cout,
    const float* __restrict__ bqp, const float* __restrict__ eqp)
{
    __shared__ __align__(16) __nv_bfloat16 Ah[128][GSTR];
    __shared__ __align__(16) __nv_bfloat16 Al[128][GSTR];
    __shared__ __align__(16) __nv_bfloat16 Wh[64][GSTR];
    __shared__ __align__(16) __nv_bfloat16 Wl[64][GSTR];

    const int tid  = threadIdx.x;
    const int wid  = tid >> 5;
    const int lane = tid & 31;
    const int g    = lane >> 2;
    const int tig  = lane & 3;
    const int m0 = blockIdx.y * 128;
    const int n0 = blockIdx.x * 64;

    const int arow = tid >> 1,  ac0 = (tid & 1) * 16;
    const int wrow = tid >> 2,  wc0 = (tid & 3) * 8;

    float o[8][4] = {};

    for (int kb = 0; kb < EMB; kb += 32) {
        const float* ap = A + (size_t)(m0 + arow) * EMB + kb + ac0;
        #pragma unroll
        for (int i = 0; i < 2; i++) {
            float4 v = *(const float4*)(ap + i*8);
            float4 w = *(const float4*)(ap + i*8 + 4);
            uint32_t h0,l0,h1,l1,h2,l2,h3,l3;
            split2(v.x, v.y, h0, l0); split2(v.z, v.w, h1, l1);
            split2(w.x, w.y, h2, l2); split2(w.z, w.w, h3, l3);
            int c = ac0 + i*8;
            *(uint32_t*)&Ah[arow][c+0] = h0; *(uint32_t*)&Ah[arow][c+2] = h1;
            *(uint32_t*)&Ah[arow][c+4] = h2; *(uint32_t*)&Ah[arow][c+6] = h3;
            *(uint32_t*)&Al[arow][c+0] = l0; *(uint32_t*)&Al[arow][c+2] = l1;
            *(uint32_t*)&Al[arow][c+4] = l2; *(uint32_t*)&Al[arow][c+6] = l3;
        }
        {
            const float* wp = W + (size_t)(n0 + wrow) * EMB + kb + wc0;
            float4 v = *(const float4*)(wp);
            float4 w = *(const float4*)(wp + 4);
            uint32_t h0,l0,h1,l1,h2,l2,h3,l3;
            split2(v.x, v.y, h0, l0); split2(v.z, v.w, h1, l1);
            split2(w.x, w.y, h2, l2); split2(w.z, w.w, h3, l3);
            *(uint32_t*)&Wh[wrow][wc0+0] = h0; *(uint32_t*)&Wh[wrow][wc0+2] = h1;
            *(uint32_t*)&Wh[wrow][wc0+4] = h2; *(uint32_t*)&Wh[wrow][wc0+6] = h3;
            *(uint32_t*)&Wl[wrow][wc0+0] = l0; *(uint32_t*)&Wl[wrow][wc0+2] = l1;
            *(uint32_t*)&Wl[wrow][wc0+4] = l2; *(uint32_t*)&Wl[wrow][wc0+6] = l3;
        }
        __syncthreads();

        #pragma unroll
        for (int u = 0; u < 2; u++) {
            const int r0 = wid*16 + g, r1 = r0 + 8, kk = u*16 + tig*2;
            uint32_t ah[4], al[4];
            ah[0] = *(const uint32_t*)&Ah[r0][kk];
            ah[1] = *(const uint32_t*)&Ah[r1][kk];
            ah[2] = *(const uint32_t*)&Ah[r0][kk+8];
            ah[3] = *(const uint32_t*)&Ah[r1][kk+8];
            al[0] = *(const uint32_t*)&Al[r0][kk];
            al[1] = *(const uint32_t*)&Al[r1][kk];
            al[2] = *(const uint32_t*)&Al[r0][kk+8];
            al[3] = *(const uint32_t*)&Al[r1][kk+8];
            #pragma unroll
            for (int j = 0; j < 8; j++) {
                uint32_t bh0 = *(const uint32_t*)&Wh[8*j+g][kk];
                uint32_t bh1 = *(const uint32_t*)&Wh[8*j+g][kk+8];
                uint32_t bl0 = *(const uint32_t*)&Wl[8*j+g][kk];
                uint32_t bl1 = *(const uint32_t*)&Wl[8*j+g][kk+8];
                mma16816(o[j], ah, bh0, bh1);
                mma16816(o[j], al, bh0, bh1);
                mma16816(o[j], ah, bl0, bl1);
            }
        }
        __syncthreads();
    }

    float qs = 1.f, qinv = 1.f, qlo = 0.f, qhi = 0.f;
    if (QUANT) {
        float b = fminf(fmaxf(*bqp, 1.0f), 8.0f);
        float e = *eqp;
        qs = exp2f(e); qinv = exp2f(-e);
        float p = exp2f(b - 1.0f);
        qlo = -p; qhi = p - 1.0f;
    }
    const int mr0 = m0 + wid*16 + g, mr1 = mr0 + 8;
    #pragma unroll
    for (int j = 0; j < 8; j++) {
        int nn = n0 + 8*j + tig*2;
        float b0 = bias[nn], b1 = bias[nn+1];
        float r[4] = { o[j][0]+b0, o[j][1]+b1, o[j][2]+b0, o[j][3]+b1 };
        if (QUANT) {
            #pragma unroll
            for (int q = 0; q < 4; q++) {
                float t = r[q] * qinv;
                t = fminf(fmaxf(t, qlo), qhi);
                r[q] = floorf(t) * qs;
            }
            __nv_bfloat16* C = (__nv_bfloat16*)Cout;
            *(uint32_t*)&C[(size_t)mr0 * EMB + nn] = pk_bf16x2(r[0], r[1]);
            *(uint32_t*)&C[(size_t)mr1 * EMB + nn] = pk_bf16x2(r[2], r[3]);
        } else {
            float* C = (float*)Cout;
            *(float2*)&C[(size_t)mr0 * EMB + nn] = make_float2(r[0], r[1]);
            *(float2*)&C[(size_t)mr1 * EMB + nn] = make_float2(r[2], r[3]);
        }
    }
}

// ---------------------------------------------------------------------------
// Flash attention on HMMA + cp.async double-buffer + ldmatrix fragments.
// 128 threads = 4 warps; BQ=64 (warp = 16 rows), BK=64, D=64.
// K row-major bf16 smem; V row-major bf16 smem (fragments via ldmatrix.trans).
// ---------------------------------------------------------------------------
#define KSTR 72                     // bf16 row stride = 144 B (16B-aligned, conflict-free)
#define TILEB (64*KSTR)             // elements per tile buffer

__global__ __launch_bounds__(128, 3) void flash_hmma(
    const __nv_bfloat16* __restrict__ gq, const __nv_bfloat16* __restrict__ gk,
    const __nv_bfloat16* __restrict__ gv, float* __restrict__ go)
{
    __shared__ __align__(16) __nv_bfloat16 Kb[2][TILEB];
    __shared__ __align__(16) __nv_bfloat16 Vb[2][TILEB];

    const int tid  = threadIdx.x;
    const int wid  = tid >> 5;
    const int lane = tid & 31;
    const int g    = lane >> 2;
    const int tig  = lane & 3;
    const int mat  = lane >> 3;    // ldmatrix matrix index
    const int lrow = lane & 7;     // ldmatrix row within matrix

    const int q0 = blockIdx.x * 64;
    const int h  = blockIdx.y;
    const int n  = blockIdx.z;

    const __nv_bfloat16* qb  = gq + ((size_t)n*SEQ + q0 + wid*16)*EMB + h*DHEAD;
    const __nv_bfloat16* kb0 = gk + (size_t)n*SEQ*EMB + h*DHEAD;
    const __nv_bfloat16* vb0 = gv + (size_t)n*SEQ*EMB + h*DHEAD;

    const uint32_t kbase[2] = { smem_u32(&Kb[0][0]), smem_u32(&Kb[1][0]) };
    const uint32_t vbase[2] = { smem_u32(&Vb[0][0]), smem_u32(&Vb[1][0]) };

    // per-thread ldmatrix offsets (bytes)
    // K (non-trans): m0=b0(j), m1=b1(j), m2=b0(j+1), m3=b1(j+1)
    const uint32_t koff = (uint32_t)(((mat>>1)*8 + lrow) * 144 + (mat&1)*16);
    // V (trans):     m0=b0(j), m1=b1(j), m2=b0(j+1), m3=b1(j+1)
    const uint32_t voff = (uint32_t)(((mat&1)*8 + lrow) * 144 + (mat>>1)*16);

    // staging indices: 512 16B-chunks per tile, 4 per thread
    const int srow = tid >> 3;        // rows 0..15 base (tid/8), row = srow + i*16
    const int sseg = tid & 7;

    // Q fragments resident in regs (bf16 gmem, direct 4B loads)
    uint32_t qa[4][4];
    {
        const __nv_bfloat16* r0 = qb + (size_t)g*EMB;
        const __nv_bfloat16* r1 = qb + (size_t)(g+8)*EMB;
        #pragma unroll
        for (int u = 0; u < 4; u++) {
            int d0 = tig*2 + 16*u;
            qa[u][0] = *(const uint32_t*)(r0 + d0);
            qa[u][1] = *(const uint32_t*)(r1 + d0);
            qa[u][2] = *(const uint32_t*)(r0 + d0 + 8);
            qa[u][3] = *(const uint32_t*)(r1 + d0 + 8);
        }
    }

    float o[8][4];
    #pragma unroll
    for (int j = 0; j < 8; j++) { o[j][0]=0.f; o[j][1]=0.f; o[j][2]=0.f; o[j][3]=0.f; }
    float m0 = -1e30f, m1 = -1e30f, l0 = 0.f, l1 = 0.f;

    const float C = 0.06375892f;  // log2(e)/sqrt(512)

    // ---- prologue: stage tile 0 into buffer 0 ----
    {
        const __nv_bfloat16* kb = kb0;
        const __nv_bfloat16* vb = vb0;
        #pragma unroll
        for (int i = 0; i < 4; i++) {
            int row = srow + i*16;
            uint32_t d = (uint32_t)(row*144 + sseg*16);
            const __nv_bfloat16* s = kb + (size_t)row*EMB + sseg*8;
            const __nv_bfloat16* t = vb + (size_t)row*EMB + sseg*8;
            cp16(kbase[0] + d, s);
            cp16(vbase[0] + d, t);
        }
        asm volatile("cp.async.commit_group;" ::: "memory");
    }

    for (int t = 0; t < SEQ/64; t++) {
        const int buf = t & 1;
        if (t + 1 < SEQ/64) {
            const __nv_bfloat16* kb = kb0 + (size_t)((t+1)*64)*EMB;
            const __nv_bfloat16* vb = vb0 + (size_t)((t+1)*64)*EMB;
            const int nb = buf ^ 1;
            #pragma unroll
            for (int i = 0; i < 4; i++) {
                int row = srow + i*16;
                uint32_t d = (uint32_t)(row*144 + sseg*16);
                cp16(kbase[nb] + d, kb + (size_t)row*EMB + sseg*8);
                cp16(vbase[nb] + d, vb + (size_t)row*EMB + sseg*8);
            }
            asm volatile("cp.async.commit_group;" ::: "memory");
            asm volatile("cp.async.wait_group 1;" ::: "memory");
        } else {
            asm volatile("cp.async.wait_group 0;" ::: "memory");
        }
        __syncthreads();

        const uint32_t kK = kbase[buf] + koff;
        const uint32_t kV = vbase[buf] + voff;

        // ---- S = Q @ K^T ----
        float sacc[8][4];
        #pragma unroll
        for (int j = 0; j < 8; j++) { sacc[j][0]=0.f; sacc[j][1]=0.f; sacc[j][2]=0.f; sacc[j][3]=0.f; }
        #pragma unroll
        for (int u = 0; u < 4; u++) {
            #pragma unroll
            for (int jp = 0; jp < 4; jp++) {
                uint32_t b00, b01, b10, b11;
                ldm4(b00, b01, b10, b11, kK + jp*2304u + u*32u);
                mma16816(sacc[2*jp],   qa[u], b00, b01);
                mma16816(sacc[2*jp+1], qa[u], b10, b11);
            }
        }

        // ---- online softmax ----
        float rm0 = -1e30f, rm1 = -1e30f;
        #pragma unroll
        for (int j = 0; j < 8; j++) {
            rm0 = fmaxf(rm0, fmaxf(sacc[j][0], sacc[j][1]));
            rm1 = fmaxf(rm1, fmaxf(sacc[j][2], sacc[j][3]));
        }
        rm0 = fmaxf(rm0, __shfl_xor_sync(0xffffffffu, rm0, 1));
        rm0 = fmaxf(rm0, __shfl_xor_sync(0xffffffffu, rm0, 2));
        rm1 = fmaxf(rm1, __shfl_xor_sync(0xffffffffu, rm1, 1));
        rm1 = fmaxf(rm1, __shfl_xor_sync(0xffffffffu, rm1, 2));

        float mn0 = fmaxf(m0, rm0), mn1 = fmaxf(m1, rm1);
        float a0 = fexp2((m0 - mn0) * C);
        float a1 = fexp2((m1 - mn1) * C);
        m0 = mn0; m1 = mn1;
        l0 *= a0;  l1 *= a1;
        float mc0 = mn0 * C, mc1 = mn1 * C;

        uint32_t phA[8], phB[8], plA[8], plB[8];
        #pragma unroll
        for (int j = 0; j < 8; j++) {
            float p0 = fexp2(fmaf(sacc[j][0], C, -mc0));
            float p1 = fexp2(fmaf(sacc[j][1], C, -mc0));
            float p2 = fexp2(fmaf(sacc[j][2], C, -mc1));
            float p3 = fexp2(fmaf(sacc[j][3], C, -mc1));
            l0 += p0 + p1;  l1 += p2 + p3;
            uint32_t h0 = __float_as_uint(p0) & 0xFFFF0000u;
            uint32_t h1 = __float_as_uint(p1) & 0xFFFF0000u;
            uint32_t h2 = __float_as_uint(p2) & 0xFFFF0000u;
            uint32_t h3 = __float_as_uint(p3) & 0xFFFF0000u;
            phA[j] = h1 | (h0 >> 16);
            phB[j] = h3 | (h2 >> 16);
            plA[j] = pk_bf16x2(p0 - __uint_as_float(h0), p1 - __uint_as_float(h1));
            plB[j] = pk_bf16x2(p2 - __uint_as_float(h2), p3 - __uint_as_float(h3));
            o[j][0] *= a0; o[j][1] *= a0; o[j][2] *= a1; o[j][3] *= a1;
        }

        // ---- O += P @ V (V fragments via ldmatrix.trans on row-major V) ----
        #pragma unroll
        for (int u = 0; u < 4; u++) {
            uint32_t ah[4] = { phA[2*u], phB[2*u], phA[2*u+1], phB[2*u+1] };
            uint32_t al[4] = { plA[2*u], plB[2*u], plA[2*u+1], plB[2*u+1] };
            #pragma unroll
            for (int jp = 0; jp < 4; jp++) {
                uint32_t c00, c01, c10, c11;
                ldm4t(c00, c01, c10, c11, kV + u*2304u + jp*32u);
                mma16816(o[2*jp],   ah, c00, c01);
                mma16816(o[2*jp],   al, c00, c01);
                mma16816(o[2*jp+1], ah, c10, c11);
                mma16816(o[2*jp+1], al, c10, c11);
            }
        }
        __syncthreads();
    }

    // ---- epilogue ----
    l0 += __shfl_xor_sync(0xffffffffu, l0, 1);
    l0 += __shfl_xor_sync(0xffffffffu, l0, 2);
    l1 += __shfl_xor_sync(0xffffffffu, l1, 1);
    l1 += __shfl_xor_sync(0xffffffffu, l1, 2);
    float i0 = 1.0f / l0, i1 = 1.0f / l1;

    float* ob = go + ((size_t)n*SEQ + q0 + wid*16)*EMB + h*DHEAD;
    #pragma unroll
    for (int j = 0; j < 8; j++) {
        *(float2*)(ob + (size_t)g*EMB + 8*j + tig*2)     = make_float2(o[j][0]*i0, o[j][1]*i0);
        *(float2*)(ob + (size_t)(g+8)*EMB + 8*j + tig*2) = make_float2(o[j][2]*i1, o[j][3]*i1);
    }
}

// ---------------------------------------------------------------------------
extern "C" void kernel_launch(void* const* d_in, const int* in_sizes, int n_in,
                              void* d_out, int out_size)
{
    const float* values = (const float*)d_in[0];
    const float* keys   = (const float*)d_in[1];
    const float* query  = (const float*)d_in[2];
    const float* Wq = (const float*)d_in[3];  const float* bq = (const float*)d_in[4];
    const float* Wk = (const float*)d_in[5];  const float* bk = (const float*)d_in[6];
    const float* Wv = (const float*)d_in[7];  const float* bv = (const float*)d_in[8];
    const float* Wo = (const float*)d_in[9];  const float* bo = (const float*)d_in[10];
    const float* bpar = (const float*)d_in[11];
    const float* epar = (const float*)d_in[12];

    __nv_bfloat16 *pq, *pk, *pv;
    float *pa;
    cudaGetSymbolAddress((void**)&pq, g_q);
    cudaGetSymbolAddress((void**)&pk, g_k);
    cudaGetSymbolAddress((void**)&pv, g_v);
    cudaGetSymbolAddress((void**)&pa, g_att);

    dim3 gblk(256);
    dim3 ggrid(EMB/64, MROWS/128);

    gemm_hmma<true><<<ggrid, gblk>>>(query,  Wq, bq, pq, bpar, epar);
    gemm_hmma<true><<<ggrid, gblk>>>(keys,   Wk, bk, pk, bpar, epar);
    gemm_hmma<true><<<ggrid, gblk>>>(values, Wv, bv, pv, bpar, epar);

    flash_hmma<<<dim3(SEQ/64, NHEAD, BATCH), 128>>>(pq, pk, pv, pa);

    gemm_hmma<false><<<ggrid, gblk>>>(pa, Wo, bo, (float*)d_out, bpar, epar);
}

// round 6
// speedup vs baseline: 3.7526x; 1.1540x over previous
#include <cuda_runtime.h>
#include <cuda_bf16.h>
#include <cstdint>
#include <math.h>

#define EMB   512
#define NHEAD 8
#define DHEAD 64
#define SEQ   2048
#define BATCH 4
#define MROWS (BATCH*SEQ)

// Scratch (no cudaMalloc allowed)
__device__ __nv_bfloat16 g_ah[MROWS*EMB], g_al[MROWS*EMB];       // split input A
__device__ __nv_bfloat16 g_wh[4*EMB*EMB], g_wl[4*EMB*EMB];       // split weights
__device__ __nv_bfloat16 g_q[MROWS*EMB], g_k[MROWS*EMB], g_v[MROWS*EMB];
__device__ __nv_bfloat16 g_oh[MROWS*EMB], g_ol[MROWS*EMB];       // attn out, pre-split

// ---------------------------------------------------------------------------
// helpers
// ---------------------------------------------------------------------------
__device__ __forceinline__ uint32_t pk_bf16x2(float lo, float hi) {
    uint32_t r;
    asm("cvt.rn.bf16x2.f32 %0, %1, %2;" : "=r"(r) : "f"(hi), "f"(lo));
    return r;
}
__device__ __forceinline__ void split2(float a, float b, uint32_t& hi, uint32_t& lo) {
    uint32_t ha = __float_as_uint(a) & 0xFFFF0000u;
    uint32_t hb = __float_as_uint(b) & 0xFFFF0000u;
    hi = hb | (ha >> 16);
    lo = pk_bf16x2(a - __uint_as_float(ha), b - __uint_as_float(hb));
}
__device__ __forceinline__ void mma16816(float* c, const uint32_t* a, uint32_t b0, uint32_t b1) {
    asm volatile(
        "mma.sync.aligned.m16n8k16.row.col.f32.bf16.bf16.f32 "
        "{%0,%1,%2,%3}, {%4,%5,%6,%7}, {%8,%9}, {%0,%1,%2,%3};"
        : "+f"(c[0]), "+f"(c[1]), "+f"(c[2]), "+f"(c[3])
        : "r"(a[0]), "r"(a[1]), "r"(a[2]), "r"(a[3]), "r"(b0), "r"(b1));
}
__device__ __forceinline__ void ldm4(uint32_t& r0, uint32_t& r1, uint32_t& r2, uint32_t& r3, uint32_t a) {
    asm volatile("ldmatrix.sync.aligned.m8n8.x4.shared.b16 {%0,%1,%2,%3}, [%4];"
        : "=r"(r0), "=r"(r1), "=r"(r2), "=r"(r3) : "r"(a));
}
__device__ __forceinline__ void ldm4t(uint32_t& r0, uint32_t& r1, uint32_t& r2, uint32_t& r3, uint32_t a) {
    asm volatile("ldmatrix.sync.aligned.m8n8.x4.trans.shared.b16 {%0,%1,%2,%3}, [%4];"
        : "=r"(r0), "=r"(r1), "=r"(r2), "=r"(r3) : "r"(a));
}
__device__ __forceinline__ void cp16(uint32_t dst, const void* src) {
    asm volatile("cp.async.ca.shared.global [%0], [%1], 16;" :: "r"(dst), "l"(src));
}
__device__ __forceinline__ uint32_t smem_u32(const void* p) {
    uint32_t a;
    asm("{ .reg .u64 t; cvta.to.shared.u64 t, %1; cvt.u32.u64 %0, t; }" : "=r"(a) : "l"(p));
    return a;
}
__device__ __forceinline__ float fexp2(float x) {
    x = fmaxf(x, -80.0f);
    float t = x + 12582912.0f;
    float n = t - 12582912.0f;
    float f = x - n;
    float p = 1.3333558146e-3f;
    p = fmaf(p, f, 9.6181291794e-3f);
    p = fmaf(p, f, 5.5504108664e-2f);
    p = fmaf(p, f, 2.4022650696e-1f);
    p = fmaf(p, f, 6.9314718056e-1f);
    p = fmaf(p, f, 1.0f);
    int ni = __float_as_int(t) - 0x4B400000;
    return __int_as_float(__float_as_int(p) + (ni << 23));
}

// ---------------------------------------------------------------------------
// split fp32 -> (hi, lo) bf16
// ---------------------------------------------------------------------------
__global__ __launch_bounds__(256) void split_fp32(
    const float4* __restrict__ in, uint2* __restrict__ hi, uint2* __restrict__ lo, int n4)
{
    int i = blockIdx.x * 256 + threadIdx.x;
    if (i < n4) {
        float4 v = in[i];
        uint32_t h0, l0, h1, l1;
        split2(v.x, v.y, h0, l0);
        split2(v.z, v.w, h1, l1);
        hi[i] = make_uint2(h0, h1);
        lo[i] = make_uint2(l0, l1);
    }
}

// ---------------------------------------------------------------------------
// bf16 pre-split GEMM: C[M,512] = A @ W^T + bias (3-product split).
// Tile 128(M) x 64(N), BK=32, 256 thr / 8 warps (4m x 2n), warp tile 32x32.
// cp.async double-buffer, ldmatrix fragments, 80B smem row stride.
// smem layout per stage (bytes): Ah@0(10240) Al@10240 Wh@20480(5120) Wl@25600. Stage=30720.
// ---------------------------------------------------------------------------
#define GEMM_SMEM (2*30720)

template<bool QUANT>
__global__ __launch_bounds__(256, 2) void gemm_bf16(
    const __nv_bfloat16* __restrict__ Agh, const __nv_bfloat16* __restrict__ Agl,
    const __nv_bfloat16* __restrict__ Wgh, const __nv_bfloat16* __restrict__ Wgl,
    const float* __restrict__ bias, void* __restrict__ Cout,
    const float* __restrict__ bqp, const float* __restrict__ eqp)
{
    extern __shared__ __align__(16) __nv_bfloat16 sm[];
    const uint32_t smb = smem_u32(sm);
    const int tid = threadIdx.x, wid = tid >> 5, lane = tid & 31;
    const int g = lane >> 2, tig = lane & 3, mat = lane >> 3, lrow = lane & 7;
    const int m0 = blockIdx.y * 128, n0 = blockIdx.x * 64;
    const int mw = (wid & 3) * 32, nw = (wid >> 2) * 32;

    // A frag order {a0,a1,a2,a3} = {(r,k0),(r+8,k0),(r,k8),(r+8,k8)}
    const uint32_t aoff = (uint32_t)((((mat & 1) * 8 + lrow) * 80) + (mat >> 1) * 16);
    // B frag order {b0(n0),b1(n0),b0(n1),b1(n1)}
    const uint32_t boff = (uint32_t)((((mat >> 1) * 8 + lrow) * 80) + (mat & 1) * 16);

    const int ar = tid >> 1, ac = (tid & 1) * 16;   // A rows 0..127, 16-elem half
    const int wr = tid >> 2, wc = (tid & 3) * 8;    // W rows 0..63,  8-elem chunk

    float o[2][4][4] = {};

    const __nv_bfloat16* a0p = Agh + (size_t)(m0 + ar) * EMB + ac;
    const __nv_bfloat16* a1p = Agl + (size_t)(m0 + ar) * EMB + ac;
    const __nv_bfloat16* w0p = Wgh + (size_t)(n0 + wr) * EMB + wc;
    const __nv_bfloat16* w1p = Wgl + (size_t)(n0 + wr) * EMB + wc;
    const uint32_t da = (uint32_t)(ar * 80 + ac * 2);
    const uint32_t dw = 20480u + (uint32_t)(wr * 80 + wc * 2);

    #define GEMM_ISSUE(s, kb) do { \
        uint32_t base = smb + (uint32_t)(s) * 30720u; \
        cp16(base + da,           a0p + (kb));      cp16(base + da + 16,          a0p + (kb) + 8); \
        cp16(base + da + 10240u,  a1p + (kb));      cp16(base + da + 10240u + 16, a1p + (kb) + 8); \
        cp16(base + dw,           w0p + (kb)); \
        cp16(base + dw + 5120u,   w1p + (kb)); \
        asm volatile("cp.async.commit_group;" ::: "memory"); \
    } while (0)

    GEMM_ISSUE(0, 0);

    for (int it = 0; it < 16; it++) {
        const int buf = it & 1;
        if (it + 1 < 16) {
            GEMM_ISSUE(buf ^ 1, (it + 1) * 32);
            asm volatile("cp.async.wait_group 1;" ::: "memory");
        } else {
            asm volatile("cp.async.wait_group 0;" ::: "memory");
        }
        __syncthreads();

        const uint32_t base = smb + (uint32_t)buf * 30720u;
        #pragma unroll
        for (int u = 0; u < 2; u++) {
            const uint32_t ka = base + (uint32_t)(mw * 80) + aoff + u * 32;
            const uint32_t kb = base + 20480u + (uint32_t)(nw * 80) + boff + u * 32;
            uint32_t AH0[4], AH1[4], AL0[4], AL1[4];
            ldm4(AH0[0], AH0[1], AH0[2], AH0[3], ka);
            ldm4(AH1[0], AH1[1], AH1[2], AH1[3], ka + 1280u);
            ldm4(AL0[0], AL0[1], AL0[2], AL0[3], ka + 10240u);
            ldm4(AL1[0], AL1[1], AL1[2], AL1[3], ka + 10240u + 1280u);
            uint32_t BH[8], BL[8];
            ldm4(BH[0], BH[1], BH[2], BH[3], kb);
            ldm4(BH[4], BH[5], BH[6], BH[7], kb + 1280u);
            ldm4(BL[0], BL[1], BL[2], BL[3], kb + 5120u);
            ldm4(BL[4], BL[5], BL[6], BL[7], kb + 5120u + 1280u);
            #pragma unroll
            for (int ni = 0; ni < 4; ni++) {
                uint32_t bh0 = BH[2*ni], bh1 = BH[2*ni+1];
                uint32_t bl0 = BL[2*ni], bl1 = BL[2*ni+1];
                mma16816(o[0][ni], AH0, bh0, bh1);
                mma16816(o[0][ni], AL0, bh0, bh1);
                mma16816(o[0][ni], AH0, bl0, bl1);
                mma16816(o[1][ni], AH1, bh0, bh1);
                mma16816(o[1][ni], AL1, bh0, bh1);
                mma16816(o[1][ni], AH1, bl0, bl1);
            }
        }
        __syncthreads();
    }

    // ---- epilogue ----
    float qs = 1.f, qinv = 1.f, qlo = 0.f, qhi = 0.f;
    if (QUANT) {
        float b = fminf(fmaxf(*bqp, 1.0f), 8.0f);
        float e = *eqp;
        qs = exp2f(e); qinv = exp2f(-e);
        float p = exp2f(b - 1.0f);
        qlo = -p; qhi = p - 1.0f;
    }
    #pragma unroll
    for (int mi = 0; mi < 2; mi++) {
        #pragma unroll
        for (int ni = 0; ni < 4; ni++) {
            int r0 = m0 + mw + mi*16 + g;
            int nn = n0 + nw + ni*8 + tig*2;
            float b0 = bias[nn], b1 = bias[nn+1];
            float r[4] = { o[mi][ni][0]+b0, o[mi][ni][1]+b1, o[mi][ni][2]+b0, o[mi][ni][3]+b1 };
            if (QUANT) {
                #pragma unroll
                for (int q = 0; q < 4; q++) {
                    float t = r[q] * qinv;
                    t = fminf(fmaxf(t, qlo), qhi);
                    r[q] = floorf(t) * qs;
                }
                __nv_bfloat16* C = (__nv_bfloat16*)Cout;
                *(uint32_t*)&C[(size_t)r0 * EMB + nn]       = pk_bf16x2(r[0], r[1]);
                *(uint32_t*)&C[(size_t)(r0+8) * EMB + nn]   = pk_bf16x2(r[2], r[3]);
            } else {
                float* C = (float*)Cout;
                *(float2*)&C[(size_t)r0 * EMB + nn]     = make_float2(r[0], r[1]);
                *(float2*)&C[(size_t)(r0+8) * EMB + nn] = make_float2(r[2], r[3]);
            }
        }
    }
}

// ---------------------------------------------------------------------------
// Flash attention on HMMA + cp.async + ldmatrix (unchanged from R5 except
// epilogue writes pre-split hi/lo bf16 for the output-projection GEMM).
// ---------------------------------------------------------------------------
#define KSTR 72
#define TILEB (64*KSTR)

__global__ __launch_bounds__(128, 3) void flash_hmma(
    const __nv_bfloat16* __restrict__ gq, const __nv_bfloat16* __restrict__ gk,
    const __nv_bfloat16* __restrict__ gv,
    __nv_bfloat16* __restrict__ goh, __nv_bfloat16* __restrict__ gol)
{
    __shared__ __align__(16) __nv_bfloat16 Kb[2][TILEB];
    __shared__ __align__(16) __nv_bfloat16 Vb[2][TILEB];

    const int tid  = threadIdx.x;
    const int wid  = tid >> 5;
    const int lane = tid & 31;
    const int g    = lane >> 2;
    const int tig  = lane & 3;
    const int mat  = lane >> 3;
    const int lrow = lane & 7;

    const int q0 = blockIdx.x * 64;
    const int h  = blockIdx.y;
    const int n  = blockIdx.z;

    const __nv_bfloat16* qb  = gq + ((size_t)n*SEQ + q0 + wid*16)*EMB + h*DHEAD;
    const __nv_bfloat16* kb0 = gk + (size_t)n*SEQ*EMB + h*DHEAD;
    const __nv_bfloat16* vb0 = gv + (size_t)n*SEQ*EMB + h*DHEAD;

    const uint32_t kbase[2] = { smem_u32(&Kb[0][0]), smem_u32(&Kb[1][0]) };
    const uint32_t vbase[2] = { smem_u32(&Vb[0][0]), smem_u32(&Vb[1][0]) };

    const uint32_t koff = (uint32_t)(((mat>>1)*8 + lrow) * 144 + (mat&1)*16);
    const uint32_t voff = (uint32_t)(((mat&1)*8 + lrow) * 144 + (mat>>1)*16);

    const int srow = tid >> 3;
    const int sseg = tid & 7;

    uint32_t qa[4][4];
    {
        const __nv_bfloat16* r0 = qb + (size_t)g*EMB;
        const __nv_bfloat16* r1 = qb + (size_t)(g+8)*EMB;
        #pragma unroll
        for (int u = 0; u < 4; u++) {
            int d0 = tig*2 + 16*u;
            qa[u][0] = *(const uint32_t*)(r0 + d0);
            qa[u][1] = *(const uint32_t*)(r1 + d0);
            qa[u][2] = *(const uint32_t*)(r0 + d0 + 8);
            qa[u][3] = *(const uint32_t*)(r1 + d0 + 8);
        }
    }

    float o[8][4];
    #pragma unroll
    for (int j = 0; j < 8; j++) { o[j][0]=0.f; o[j][1]=0.f; o[j][2]=0.f; o[j][3]=0.f; }
    float m0 = -1e30f, m1 = -1e30f, l0 = 0.f, l1 = 0.f;

    const float C = 0.06375892f;  // log2(e)/sqrt(512)

    {
        #pragma unroll
        for (int i = 0; i < 4; i++) {
            int row = srow + i*16;
            uint32_t d = (uint32_t)(row*144 + sseg*16);
            cp16(kbase[0] + d, kb0 + (size_t)row*EMB + sseg*8);
            cp16(vbase[0] + d, vb0 + (size_t)row*EMB + sseg*8);
        }
        asm volatile("cp.async.commit_group;" ::: "memory");
    }

    for (int t = 0; t < SEQ/64; t++) {
        const int buf = t & 1;
        if (t + 1 < SEQ/64) {
            const __nv_bfloat16* kb = kb0 + (size_t)((t+1)*64)*EMB;
            const __nv_bfloat16* vb = vb0 + (size_t)((t+1)*64)*EMB;
            const int nb = buf ^ 1;
            #pragma unroll
            for (int i = 0; i < 4; i++) {
                int row = srow + i*16;
                uint32_t d = (uint32_t)(row*144 + sseg*16);
                cp16(kbase[nb] + d, kb + (size_t)row*EMB + sseg*8);
                cp16(vbase[nb] + d, vb + (size_t)row*EMB + sseg*8);
            }
            asm volatile("cp.async.commit_group;" ::: "memory");
            asm volatile("cp.async.wait_group 1;" ::: "memory");
        } else {
            asm volatile("cp.async.wait_group 0;" ::: "memory");
        }
        __syncthreads();

        const uint32_t kK = kbase[buf] + koff;
        const uint32_t kV = vbase[buf] + voff;

        float sacc[8][4];
        #pragma unroll
        for (int j = 0; j < 8; j++) { sacc[j][0]=0.f; sacc[j][1]=0.f; sacc[j][2]=0.f; sacc[j][3]=0.f; }
        #pragma unroll
        for (int u = 0; u < 4; u++) {
            #pragma unroll
            for (int jp = 0; jp < 4; jp++) {
                uint32_t b00, b01, b10, b11;
                ldm4(b00, b01, b10, b11, kK + jp*2304u + u*32u);
                mma16816(sacc[2*jp],   qa[u], b00, b01);
                mma16816(sacc[2*jp+1], qa[u], b10, b11);
            }
        }

        float rm0 = -1e30f, rm1 = -1e30f;
        #pragma unroll
        for (int j = 0; j < 8; j++) {
            rm0 = fmaxf(rm0, fmaxf(sacc[j][0], sacc[j][1]));
            rm1 = fmaxf(rm1, fmaxf(sacc[j][2], sacc[j][3]));
        }
        rm0 = fmaxf(rm0, __shfl_xor_sync(0xffffffffu, rm0, 1));
        rm0 = fmaxf(rm0, __shfl_xor_sync(0xffffffffu, rm0, 2));
        rm1 = fmaxf(rm1, __shfl_xor_sync(0xffffffffu, rm1, 1));
        rm1 = fmaxf(rm1, __shfl_xor_sync(0xffffffffu, rm1, 2));

        float mn0 = fmaxf(m0, rm0), mn1 = fmaxf(m1, rm1);
        float a0 = fexp2((m0 - mn0) * C);
        float a1 = fexp2((m1 - mn1) * C);
        m0 = mn0; m1 = mn1;
        l0 *= a0;  l1 *= a1;
        float mc0 = mn0 * C, mc1 = mn1 * C;

        uint32_t phA[8], phB[8], plA[8], plB[8];
        #pragma unroll
        for (int j = 0; j < 8; j++) {
            float p0 = fexp2(fmaf(sacc[j][0], C, -mc0));
            float p1 = fexp2(fmaf(sacc[j][1], C, -mc0));
            float p2 = fexp2(fmaf(sacc[j][2], C, -mc1));
            float p3 = fexp2(fmaf(sacc[j][3], C, -mc1));
            l0 += p0 + p1;  l1 += p2 + p3;
            uint32_t h0 = __float_as_uint(p0) & 0xFFFF0000u;
            uint32_t h1 = __float_as_uint(p1) & 0xFFFF0000u;
            uint32_t h2 = __float_as_uint(p2) & 0xFFFF0000u;
            uint32_t h3 = __float_as_uint(p3) & 0xFFFF0000u;
            phA[j] = h1 | (h0 >> 16);
            phB[j] = h3 | (h2 >> 16);
            plA[j] = pk_bf16x2(p0 - __uint_as_float(h0), p1 - __uint_as_float(h1));
            plB[j] = pk_bf16x2(p2 - __uint_as_float(h2), p3 - __uint_as_float(h3));
            o[j][0] *= a0; o[j][1] *= a0; o[j][2] *= a1; o[j][3] *= a1;
        }

        #pragma unroll
        for (int u = 0; u < 4; u++) {
            uint32_t ah[4] = { phA[2*u], phB[2*u], phA[2*u+1], phB[2*u+1] };
            uint32_t al[4] = { plA[2*u], plB[2*u], plA[2*u+1], plB[2*u+1] };
            #pragma unroll
            for (int jp = 0; jp < 4; jp++) {
                uint32_t c00, c01, c10, c11;
                ldm4t(c00, c01, c10, c11, kV + u*2304u + jp*32u);
                mma16816(o[2*jp],   ah, c00, c01);
                mma16816(o[2*jp],   al, c00, c01);
                mma16816(o[2*jp+1], ah, c10, c11);
                mma16816(o[2*jp+1], al, c10, c11);
            }
        }
        __syncthreads();
    }

    l0 += __shfl_xor_sync(0xffffffffu, l0, 1);
    l0 += __shfl_xor_sync(0xffffffffu, l0, 2);
    l1 += __shfl_xor_sync(0xffffffffu, l1, 1);
    l1 += __shfl_xor_sync(0xffffffffu, l1, 2);
    float i0 = 1.0f / l0, i1 = 1.0f / l1;

    const size_t ob = ((size_t)n*SEQ + q0 + wid*16)*EMB + h*DHEAD;
    #pragma unroll
    for (int j = 0; j < 8; j++) {
        int nn = 8*j + tig*2;
        uint32_t h0, l0u, h1, l1u;
        split2(o[j][0]*i0, o[j][1]*i0, h0, l0u);
        split2(o[j][2]*i1, o[j][3]*i1, h1, l1u);
        *(uint32_t*)&goh[ob + (size_t)g*EMB + nn]     = h0;
        *(uint32_t*)&gol[ob + (size_t)g*EMB + nn]     = l0u;
        *(uint32_t*)&goh[ob + (size_t)(g+8)*EMB + nn] = h1;
        *(uint32_t*)&gol[ob + (size_t)(g+8)*EMB + nn] = l1u;
    }
}

// ---------------------------------------------------------------------------
extern "C" void kernel_launch(void* const* d_in, const int* in_sizes, int n_in,
                              void* d_out, int out_size)
{
    const float* values = (const float*)d_in[0];
    const float* keys   = (const float*)d_in[1];
    const float* query  = (const float*)d_in[2];
    const float* Wq = (const float*)d_in[3];  const float* bq = (const float*)d_in[4];
    const float* Wk = (const float*)d_in[5];  const float* bk = (const float*)d_in[6];
    const float* Wv = (const float*)d_in[7];  const float* bv = (const float*)d_in[8];
    const float* Wo = (const float*)d_in[9];  const float* bo = (const float*)d_in[10];
    const float* bpar = (const float*)d_in[11];
    const float* epar = (const float*)d_in[12];

    __nv_bfloat16 *ah, *al, *wh, *wl, *pq, *pk, *pv, *oh, *ol;
    cudaGetSymbolAddress((void**)&ah, g_ah);
    cudaGetSymbolAddress((void**)&al, g_al);
    cudaGetSymbolAddress((void**)&wh, g_wh);
    cudaGetSymbolAddress((void**)&wl, g_wl);
    cudaGetSymbolAddress((void**)&pq, g_q);
    cudaGetSymbolAddress((void**)&pk, g_k);
    cudaGetSymbolAddress((void**)&pv, g_v);
    cudaGetSymbolAddress((void**)&oh, g_oh);
    cudaGetSymbolAddress((void**)&ol, g_ol);

    const int N4  = MROWS*EMB/4;   // input elems / 4
    const int NW4 = EMB*EMB/4;     // weight elems / 4

    cudaFuncSetAttribute(gemm_bf16<true>,  cudaFuncAttributeMaxDynamicSharedMemorySize, GEMM_SMEM);
    cudaFuncSetAttribute(gemm_bf16<false>, cudaFuncAttributeMaxDynamicSharedMemorySize, GEMM_SMEM);

    // split the 4 weight matrices
    split_fp32<<<NW4/256, 256>>>((const float4*)Wq, (uint2*)(wh + 0*EMB*EMB), (uint2*)(wl + 0*EMB*EMB), NW4);
    split_fp32<<<NW4/256, 256>>>((const float4*)Wk, (uint2*)(wh + 1*EMB*EMB), (uint2*)(wl + 1*EMB*EMB), NW4);
    split_fp32<<<NW4/256, 256>>>((const float4*)Wv, (uint2*)(wh + 2*EMB*EMB), (uint2*)(wl + 2*EMB*EMB), NW4);
    split_fp32<<<NW4/256, 256>>>((const float4*)Wo, (uint2*)(wh + 3*EMB*EMB), (uint2*)(wl + 3*EMB*EMB), NW4);

    dim3 ggrid(EMB/64, MROWS/128);
    dim3 gblk(256);

    split_fp32<<<N4/256, 256>>>((const float4*)query, (uint2*)ah, (uint2*)al, N4);
    gemm_bf16<true><<<ggrid, gblk, GEMM_SMEM>>>(ah, al, wh + 0*EMB*EMB, wl + 0*EMB*EMB, bq, pq, bpar, epar);

    split_fp32<<<N4/256, 256>>>((const float4*)keys, (uint2*)ah, (uint2*)al, N4);
    gemm_bf16<true><<<ggrid, gblk, GEMM_SMEM>>>(ah, al, wh + 1*EMB*EMB, wl + 1*EMB*EMB, bk, pk, bpar, epar);

    split_fp32<<<N4/256, 256>>>((const float4*)values, (uint2*)ah, (uint2*)al, N4);
    gemm_bf16<true><<<ggrid, gblk, GEMM_SMEM>>>(ah, al, wh + 2*EMB*EMB, wl + 2*EMB*EMB, bv, pv, bpar, epar);

    flash_hmma<<<dim3(SEQ/64, NHEAD, BATCH), 128>>>(pq, pk, pv, oh, ol);

    gemm_bf16<false><<<ggrid, gblk, GEMM_SMEM>>>(oh, ol, wh + 3*EMB*EMB, wl + 3*EMB*EMB, bo, (float*)d_out, bpar, epar);
}

// round 7
// speedup vs baseline: 4.0127x; 1.0693x over previous
#include <cuda_runtime.h>
#include <cuda_bf16.h>
#include <cstdint>
#include <math.h>

#define EMB   512
#define NHEAD 8
#define DHEAD 64
#define SEQ   2048
#define BATCH 4
#define MROWS (BATCH*SEQ)

// Scratch (no cudaMalloc allowed)
__device__ __nv_bfloat16 g_ah[MROWS*EMB], g_al[MROWS*EMB];       // split input A
__device__ __nv_bfloat16 g_wh[4*EMB*EMB], g_wl[4*EMB*EMB];       // split weights
__device__ __nv_bfloat16 g_q[MROWS*EMB], g_k[MROWS*EMB], g_v[MROWS*EMB];
__device__ __nv_bfloat16 g_oh[MROWS*EMB], g_ol[MROWS*EMB];       // attn out, pre-split

// ---------------------------------------------------------------------------
// helpers
// ---------------------------------------------------------------------------
__device__ __forceinline__ uint32_t pk_bf16x2(float lo, float hi) {
    uint32_t r;
    asm("cvt.rn.bf16x2.f32 %0, %1, %2;" : "=r"(r) : "f"(hi), "f"(lo));
    return r;
}
__device__ __forceinline__ void split2(float a, float b, uint32_t& hi, uint32_t& lo) {
    uint32_t ha = __float_as_uint(a) & 0xFFFF0000u;
    uint32_t hb = __float_as_uint(b) & 0xFFFF0000u;
    hi = hb | (ha >> 16);
    lo = pk_bf16x2(a - __uint_as_float(ha), b - __uint_as_float(hb));
}
__device__ __forceinline__ void mma16816(float* c, const uint32_t* a, uint32_t b0, uint32_t b1) {
    asm volatile(
        "mma.sync.aligned.m16n8k16.row.col.f32.bf16.bf16.f32 "
        "{%0,%1,%2,%3}, {%4,%5,%6,%7}, {%8,%9}, {%0,%1,%2,%3};"
        : "+f"(c[0]), "+f"(c[1]), "+f"(c[2]), "+f"(c[3])
        : "r"(a[0]), "r"(a[1]), "r"(a[2]), "r"(a[3]), "r"(b0), "r"(b1));
}
__device__ __forceinline__ void ldm4(uint32_t& r0, uint32_t& r1, uint32_t& r2, uint32_t& r3, uint32_t a) {
    asm volatile("ldmatrix.sync.aligned.m8n8.x4.shared.b16 {%0,%1,%2,%3}, [%4];"
        : "=r"(r0), "=r"(r1), "=r"(r2), "=r"(r3) : "r"(a));
}
__device__ __forceinline__ void ldm4t(uint32_t& r0, uint32_t& r1, uint32_t& r2, uint32_t& r3, uint32_t a) {
    asm volatile("ldmatrix.sync.aligned.m8n8.x4.trans.shared.b16 {%0,%1,%2,%3}, [%4];"
        : "=r"(r0), "=r"(r1), "=r"(r2), "=r"(r3) : "r"(a));
}
__device__ __forceinline__ void cp16(uint32_t dst, const void* src) {
    asm volatile("cp.async.ca.shared.global [%0], [%1], 16;" :: "r"(dst), "l"(src));
}
__device__ __forceinline__ uint32_t smem_u32(const void* p) {
    uint32_t a;
    asm("{ .reg .u64 t; cvta.to.shared.u64 t, %1; cvt.u32.u64 %0, t; }" : "=r"(a) : "l"(p));
    return a;
}
// MUFU exp2 (single SASS op, rel err ~2^-22)
__device__ __forceinline__ float mexp2(float x) {
    float r;
    asm("ex2.approx.f32 %0, %1;" : "=f"(r) : "f"(x));
    return r;
}

// ---------------------------------------------------------------------------
// split fp32 -> (hi, lo) bf16
// ---------------------------------------------------------------------------
__global__ __launch_bounds__(256) void split_fp32(
    const float4* __restrict__ in, uint2* __restrict__ hi, uint2* __restrict__ lo, int n4)
{
    int i = blockIdx.x * 256 + threadIdx.x;
    if (i < n4) {
        float4 v = in[i];
        uint32_t h0, l0, h1, l1;
        split2(v.x, v.y, h0, l0);
        split2(v.z, v.w, h1, l1);
        hi[i] = make_uint2(h0, h1);
        lo[i] = make_uint2(l0, l1);
    }
}

// ---------------------------------------------------------------------------
// bf16 pre-split GEMM: C[M,512] = A @ W^T + bias (3-product split).
// Tile 128(M) x 64(N), BK=32, 256 thr / 8 warps (4m x 2n), warp tile 32x32.
// cp.async double-buffer, ldmatrix fragments, 80B smem row stride.
// ---------------------------------------------------------------------------
#define GEMM_SMEM (2*30720)

template<bool QUANT>
__global__ __launch_bounds__(256, 2) void gemm_bf16(
    const __nv_bfloat16* __restrict__ Agh, const __nv_bfloat16* __restrict__ Agl,
    const __nv_bfloat16* __restrict__ Wgh, const __nv_bfloat16* __restrict__ Wgl,
    const float* __restrict__ bias, void* __restrict__ Cout,
    const float* __restrict__ bqp, const float* __restrict__ eqp)
{
    extern __shared__ __align__(16) __nv_bfloat16 sm[];
    const uint32_t smb = smem_u32(sm);
    const int tid = threadIdx.x, wid = tid >> 5, lane = tid & 31;
    const int g = lane >> 2, tig = lane & 3, mat = lane >> 3, lrow = lane & 7;
    const int m0 = blockIdx.y * 128, n0 = blockIdx.x * 64;
    const int mw = (wid & 3) * 32, nw = (wid >> 2) * 32;

    const uint32_t aoff = (uint32_t)((((mat & 1) * 8 + lrow) * 80) + (mat >> 1) * 16);
    const uint32_t boff = (uint32_t)((((mat >> 1) * 8 + lrow) * 80) + (mat & 1) * 16);

    const int ar = tid >> 1, ac = (tid & 1) * 16;
    const int wr = tid >> 2, wc = (tid & 3) * 8;

    float o[2][4][4] = {};

    const __nv_bfloat16* a0p = Agh + (size_t)(m0 + ar) * EMB + ac;
    const __nv_bfloat16* a1p = Agl + (size_t)(m0 + ar) * EMB + ac;
    const __nv_bfloat16* w0p = Wgh + (size_t)(n0 + wr) * EMB + wc;
    const __nv_bfloat16* w1p = Wgl + (size_t)(n0 + wr) * EMB + wc;
    const uint32_t da = (uint32_t)(ar * 80 + ac * 2);
    const uint32_t dw = 20480u + (uint32_t)(wr * 80 + wc * 2);

    #define GEMM_ISSUE(s, kb) do { \
        uint32_t base = smb + (uint32_t)(s) * 30720u; \
        cp16(base + da,           a0p + (kb));      cp16(base + da + 16,          a0p + (kb) + 8); \
        cp16(base + da + 10240u,  a1p + (kb));      cp16(base + da + 10240u + 16, a1p + (kb) + 8); \
        cp16(base + dw,           w0p + (kb)); \
        cp16(base + dw + 5120u,   w1p + (kb)); \
        asm volatile("cp.async.commit_group;" ::: "memory"); \
    } while (0)

    GEMM_ISSUE(0, 0);

    for (int it = 0; it < 16; it++) {
        const int buf = it & 1;
        if (it + 1 < 16) {
            GEMM_ISSUE(buf ^ 1, (it + 1) * 32);
            asm volatile("cp.async.wait_group 1;" ::: "memory");
        } else {
            asm volatile("cp.async.wait_group 0;" ::: "memory");
        }
        __syncthreads();

        const uint32_t base = smb + (uint32_t)buf * 30720u;
        #pragma unroll
        for (int u = 0; u < 2; u++) {
            const uint32_t ka = base + (uint32_t)(mw * 80) + aoff + u * 32;
            const uint32_t kb = base + 20480u + (uint32_t)(nw * 80) + boff + u * 32;
            uint32_t AH0[4], AH1[4], AL0[4], AL1[4];
            ldm4(AH0[0], AH0[1], AH0[2], AH0[3], ka);
            ldm4(AH1[0], AH1[1], AH1[2], AH1[3], ka + 1280u);
            ldm4(AL0[0], AL0[1], AL0[2], AL0[3], ka + 10240u);
            ldm4(AL1[0], AL1[1], AL1[2], AL1[3], ka + 10240u + 1280u);
            uint32_t BH[8], BL[8];
            ldm4(BH[0], BH[1], BH[2], BH[3], kb);
            ldm4(BH[4], BH[5], BH[6], BH[7], kb + 1280u);
            ldm4(BL[0], BL[1], BL[2], BL[3], kb + 5120u);
            ldm4(BL[4], BL[5], BL[6], BL[7], kb + 5120u + 1280u);
            #pragma unroll
            for (int ni = 0; ni < 4; ni++) {
                uint32_t bh0 = BH[2*ni], bh1 = BH[2*ni+1];
                uint32_t bl0 = BL[2*ni], bl1 = BL[2*ni+1];
                mma16816(o[0][ni], AH0, bh0, bh1);
                mma16816(o[0][ni], AL0, bh0, bh1);
                mma16816(o[0][ni], AH0, bl0, bl1);
                mma16816(o[1][ni], AH1, bh0, bh1);
                mma16816(o[1][ni], AL1, bh0, bh1);
                mma16816(o[1][ni], AH1, bl0, bl1);
            }
        }
        __syncthreads();
    }

    float qs = 1.f, qinv = 1.f, qlo = 0.f, qhi = 0.f;
    if (QUANT) {
        float b = fminf(fmaxf(*bqp, 1.0f), 8.0f);
        float e = *eqp;
        qs = exp2f(e); qinv = exp2f(-e);
        float p = exp2f(b - 1.0f);
        qlo = -p; qhi = p - 1.0f;
    }
    #pragma unroll
    for (int mi = 0; mi < 2; mi++) {
        #pragma unroll
        for (int ni = 0; ni < 4; ni++) {
            int r0 = m0 + mw + mi*16 + g;
            int nn = n0 + nw + ni*8 + tig*2;
            float b0 = bias[nn], b1 = bias[nn+1];
            float r[4] = { o[mi][ni][0]+b0, o[mi][ni][1]+b1, o[mi][ni][2]+b0, o[mi][ni][3]+b1 };
            if (QUANT) {
                #pragma unroll
                for (int q = 0; q < 4; q++) {
                    float t = r[q] * qinv;
                    t = fminf(fmaxf(t, qlo), qhi);
                    r[q] = floorf(t) * qs;
                }
                __nv_bfloat16* C = (__nv_bfloat16*)Cout;
                *(uint32_t*)&C[(size_t)r0 * EMB + nn]       = pk_bf16x2(r[0], r[1]);
                *(uint32_t*)&C[(size_t)(r0+8) * EMB + nn]   = pk_bf16x2(r[2], r[3]);
            } else {
                float* C = (float*)Cout;
                *(float2*)&C[(size_t)r0 * EMB + nn]     = make_float2(r[0], r[1]);
                *(float2*)&C[(size_t)(r0+8) * EMB + nn] = make_float2(r[2], r[3]);
            }
        }
    }
}

// ---------------------------------------------------------------------------
// Flash attention on HMMA + cp.async + ldmatrix. MUFU exp + max-hysteresis.
// ---------------------------------------------------------------------------
#define KSTR 72
#define TILEB (64*KSTR)
#define MARG 15.0f   // hysteresis margin in s-units (~1.0 in log2)

__global__ __launch_bounds__(128, 3) void flash_hmma(
    const __nv_bfloat16* __restrict__ gq, const __nv_bfloat16* __restrict__ gk,
    const __nv_bfloat16* __restrict__ gv,
    __nv_bfloat16* __restrict__ goh, __nv_bfloat16* __restrict__ gol)
{
    __shared__ __align__(16) __nv_bfloat16 Kb[2][TILEB];
    __shared__ __align__(16) __nv_bfloat16 Vb[2][TILEB];

    const int tid  = threadIdx.x;
    const int wid  = tid >> 5;
    const int lane = tid & 31;
    const int g    = lane >> 2;
    const int tig  = lane & 3;
    const int mat  = lane >> 3;
    const int lrow = lane & 7;

    const int q0 = blockIdx.x * 64;
    const int h  = blockIdx.y;
    const int n  = blockIdx.z;

    const __nv_bfloat16* qb  = gq + ((size_t)n*SEQ + q0 + wid*16)*EMB + h*DHEAD;
    const __nv_bfloat16* kb0 = gk + (size_t)n*SEQ*EMB + h*DHEAD;
    const __nv_bfloat16* vb0 = gv + (size_t)n*SEQ*EMB + h*DHEAD;

    const uint32_t kbase[2] = { smem_u32(&Kb[0][0]), smem_u32(&Kb[1][0]) };
    const uint32_t vbase[2] = { smem_u32(&Vb[0][0]), smem_u32(&Vb[1][0]) };

    const uint32_t koff = (uint32_t)(((mat>>1)*8 + lrow) * 144 + (mat&1)*16);
    const uint32_t voff = (uint32_t)(((mat&1)*8 + lrow) * 144 + (mat>>1)*16);

    const int srow = tid >> 3;
    const int sseg = tid & 7;

    uint32_t qa[4][4];
    {
        const __nv_bfloat16* r0 = qb + (size_t)g*EMB;
        const __nv_bfloat16* r1 = qb + (size_t)(g+8)*EMB;
        #pragma unroll
        for (int u = 0; u < 4; u++) {
            int d0 = tig*2 + 16*u;
            qa[u][0] = *(const uint32_t*)(r0 + d0);
            qa[u][1] = *(const uint32_t*)(r1 + d0);
            qa[u][2] = *(const uint32_t*)(r0 + d0 + 8);
            qa[u][3] = *(const uint32_t*)(r1 + d0 + 8);
        }
    }

    float o[8][4];
    #pragma unroll
    for (int j = 0; j < 8; j++) { o[j][0]=0.f; o[j][1]=0.f; o[j][2]=0.f; o[j][3]=0.f; }
    float m0 = 0.f, m1 = 0.f, l0 = 0.f, l1 = 0.f;

    const float C = 0.06375892f;  // log2(e)/sqrt(512)

    {
        #pragma unroll
        for (int i = 0; i < 4; i++) {
            int row = srow + i*16;
            uint32_t d = (uint32_t)(row*144 + sseg*16);
            cp16(kbase[0] + d, kb0 + (size_t)row*EMB + sseg*8);
            cp16(vbase[0] + d, vb0 + (size_t)row*EMB + sseg*8);
        }
        asm volatile("cp.async.commit_group;" ::: "memory");
    }

    for (int t = 0; t < SEQ/64; t++) {
        const int buf = t & 1;
        if (t + 1 < SEQ/64) {
            const __nv_bfloat16* kb = kb0 + (size_t)((t+1)*64)*EMB;
            const __nv_bfloat16* vb = vb0 + (size_t)((t+1)*64)*EMB;
            const int nb = buf ^ 1;
            #pragma unroll
            for (int i = 0; i < 4; i++) {
                int row = srow + i*16;
                uint32_t d = (uint32_t)(row*144 + sseg*16);
                cp16(kbase[nb] + d, kb + (size_t)row*EMB + sseg*8);
                cp16(vbase[nb] + d, vb + (size_t)row*EMB + sseg*8);
            }
            asm volatile("cp.async.commit_group;" ::: "memory");
            asm volatile("cp.async.wait_group 1;" ::: "memory");
        } else {
            asm volatile("cp.async.wait_group 0;" ::: "memory");
        }
        __syncthreads();

        const uint32_t kK = kbase[buf] + koff;
        const uint32_t kV = vbase[buf] + voff;

        // ---- S = Q @ K^T ----
        float sacc[8][4];
        #pragma unroll
        for (int j = 0; j < 8; j++) { sacc[j][0]=0.f; sacc[j][1]=0.f; sacc[j][2]=0.f; sacc[j][3]=0.f; }
        #pragma unroll
        for (int u = 0; u < 4; u++) {
            #pragma unroll
            for (int jp = 0; jp < 4; jp++) {
                uint32_t b00, b01, b10, b11;
                ldm4(b00, b01, b10, b11, kK + jp*2304u + u*32u);
                mma16816(sacc[2*jp],   qa[u], b00, b01);
                mma16816(sacc[2*jp+1], qa[u], b10, b11);
            }
        }

        // ---- online softmax (MUFU exp, hysteresis max) ----
        float rm0 = sacc[0][0], rm1 = sacc[0][2];
        rm0 = fmaxf(rm0, sacc[0][1]); rm1 = fmaxf(rm1, sacc[0][3]);
        #pragma unroll
        for (int j = 1; j < 8; j++) {
            rm0 = fmaxf(rm0, fmaxf(sacc[j][0], sacc[j][1]));
            rm1 = fmaxf(rm1, fmaxf(sacc[j][2], sacc[j][3]));
        }
        rm0 = fmaxf(rm0, __shfl_xor_sync(0xffffffffu, rm0, 1));
        rm0 = fmaxf(rm0, __shfl_xor_sync(0xffffffffu, rm0, 2));
        rm1 = fmaxf(rm1, __shfl_xor_sync(0xffffffffu, rm1, 1));
        rm1 = fmaxf(rm1, __shfl_xor_sync(0xffffffffu, rm1, 2));

        if (t == 0) {
            m0 = rm0 + MARG;
            m1 = rm1 + MARG;
        } else if (rm0 > m0 || rm1 > m1) {
            float a0 = 1.0f, a1 = 1.0f;
            if (rm0 > m0) { float nm = rm0 + MARG; a0 = mexp2((m0 - nm) * C); m0 = nm; }
            if (rm1 > m1) { float nm = rm1 + MARG; a1 = mexp2((m1 - nm) * C); m1 = nm; }
            l0 *= a0;  l1 *= a1;
            #pragma unroll
            for (int j = 0; j < 8; j++) {
                o[j][0] *= a0; o[j][1] *= a0; o[j][2] *= a1; o[j][3] *= a1;
            }
        }
        float mc0 = m0 * C, mc1 = m1 * C;

        uint32_t phA[8], phB[8], plA[8], plB[8];
        #pragma unroll
        for (int j = 0; j < 8; j++) {
            float p0 = mexp2(fmaf(sacc[j][0], C, -mc0));
            float p1 = mexp2(fmaf(sacc[j][1], C, -mc0));
            float p2 = mexp2(fmaf(sacc[j][2], C, -mc1));
            float p3 = mexp2(fmaf(sacc[j][3], C, -mc1));
            l0 += p0 + p1;  l1 += p2 + p3;
            uint32_t h0 = __float_as_uint(p0) & 0xFFFF0000u;
            uint32_t h1 = __float_as_uint(p1) & 0xFFFF0000u;
            uint32_t h2 = __float_as_uint(p2) & 0xFFFF0000u;
            uint32_t h3 = __float_as_uint(p3) & 0xFFFF0000u;
            phA[j] = h1 | (h0 >> 16);
            phB[j] = h3 | (h2 >> 16);
            plA[j] = pk_bf16x2(p0 - __uint_as_float(h0), p1 - __uint_as_float(h1));
            plB[j] = pk_bf16x2(p2 - __uint_as_float(h2), p3 - __uint_as_float(h3));
        }

        // ---- O += P @ V ----
        #pragma unroll
        for (int u = 0; u < 4; u++) {
            uint32_t ah[4] = { phA[2*u], phB[2*u], phA[2*u+1], phB[2*u+1] };
            uint32_t al[4] = { plA[2*u], plB[2*u], plA[2*u+1], plB[2*u+1] };
            #pragma unroll
            for (int jp = 0; jp < 4; jp++) {
                uint32_t c00, c01, c10, c11;
                ldm4t(c00, c01, c10, c11, kV + u*2304u + jp*32u);
                mma16816(o[2*jp],   ah, c00, c01);
                mma16816(o[2*jp],   al, c00, c01);
                mma16816(o[2*jp+1], ah, c10, c11);
                mma16816(o[2*jp+1], al, c10, c11);
            }
        }
        __syncthreads();
    }

    l0 += __shfl_xor_sync(0xffffffffu, l0, 1);
    l0 += __shfl_xor_sync(0xffffffffu, l0, 2);
    l1 += __shfl_xor_sync(0xffffffffu, l1, 1);
    l1 += __shfl_xor_sync(0xffffffffu, l1, 2);
    float i0 = 1.0f / l0, i1 = 1.0f / l1;

    const size_t ob = ((size_t)n*SEQ + q0 + wid*16)*EMB + h*DHEAD;
    #pragma unroll
    for (int j = 0; j < 8; j++) {
        int nn = 8*j + tig*2;
        uint32_t h0, l0u, h1, l1u;
        split2(o[j][0]*i0, o[j][1]*i0, h0, l0u);
        split2(o[j][2]*i1, o[j][3]*i1, h1, l1u);
        *(uint32_t*)&goh[ob + (size_t)g*EMB + nn]     = h0;
        *(uint32_t*)&gol[ob + (size_t)g*EMB + nn]     = l0u;
        *(uint32_t*)&goh[ob + (size_t)(g+8)*EMB + nn] = h1;
        *(uint32_t*)&gol[ob + (size_t)(g+8)*EMB + nn] = l1u;
    }
}

// ---------------------------------------------------------------------------
extern "C" void kernel_launch(void* const* d_in, const int* in_sizes, int n_in,
                              void* d_out, int out_size)
{
    const float* values = (const float*)d_in[0];
    const float* keys   = (const float*)d_in[1];
    const float* query  = (const float*)d_in[2];
    const float* Wq = (const float*)d_in[3];  const float* bq = (const float*)d_in[4];
    const float* Wk = (const float*)d_in[5];  const float* bk = (const float*)d_in[6];
    const float* Wv = (const float*)d_in[7];  const float* bv = (const float*)d_in[8];
    const float* Wo = (const float*)d_in[9];  const float* bo = (const float*)d_in[10];
    const float* bpar = (const float*)d_in[11];
    const float* epar = (const float*)d_in[12];

    __nv_bfloat16 *ah, *al, *wh, *wl, *pq, *pk, *pv, *oh, *ol;
    cudaGetSymbolAddress((void**)&ah, g_ah);
    cudaGetSymbolAddress((void**)&al, g_al);
    cudaGetSymbolAddress((void**)&wh, g_wh);
    cudaGetSymbolAddress((void**)&wl, g_wl);
    cudaGetSymbolAddress((void**)&pq, g_q);
    cudaGetSymbolAddress((void**)&pk, g_k);
    cudaGetSymbolAddress((void**)&pv, g_v);
    cudaGetSymbolAddress((void**)&oh, g_oh);
    cudaGetSymbolAddress((void**)&ol, g_ol);

    const int N4  = MROWS*EMB/4;
    const int NW4 = EMB*EMB/4;

    cudaFuncSetAttribute(gemm_bf16<true>,  cudaFuncAttributeMaxDynamicSharedMemorySize, GEMM_SMEM);
    cudaFuncSetAttribute(gemm_bf16<false>, cudaFuncAttributeMaxDynamicSharedMemorySize, GEMM_SMEM);

    split_fp32<<<NW4/256, 256>>>((const float4*)Wq, (uint2*)(wh + 0*EMB*EMB), (uint2*)(wl + 0*EMB*EMB), NW4);
    split_fp32<<<NW4/256, 256>>>((const float4*)Wk, (uint2*)(wh + 1*EMB*EMB), (uint2*)(wl + 1*EMB*EMB), NW4);
    split_fp32<<<NW4/256, 256>>>((const float4*)Wv, (uint2*)(wh + 2*EMB*EMB), (uint2*)(wl + 2*EMB*EMB), NW4);
    split_fp32<<<NW4/256, 256>>>((const float4*)Wo, (uint2*)(wh + 3*EMB*EMB), (uint2*)(wl + 3*EMB*EMB), NW4);

    dim3 ggrid(EMB/64, MROWS/128);
    dim3 gblk(256);

    split_fp32<<<N4/256, 256>>>((const float4*)query, (uint2*)ah, (uint2*)al, N4);
    gemm_bf16<true><<<ggrid, gblk, GEMM_SMEM>>>(ah, al, wh + 0*EMB*EMB, wl + 0*EMB*EMB, bq, pq, bpar, epar);

    split_fp32<<<N4/256, 256>>>((const float4*)keys, (uint2*)ah, (uint2*)al, N4);
    gemm_bf16<true><<<ggrid, gblk, GEMM_SMEM>>>(ah, al, wh + 1*EMB*EMB, wl + 1*EMB*EMB, bk, pk, bpar, epar);

    split_fp32<<<N4/256, 256>>>((const float4*)values, (uint2*)ah, (uint2*)al, N4);
    gemm_bf16<true><<<ggrid, gblk, GEMM_SMEM>>>(ah, al, wh + 2*EMB*EMB, wl + 2*EMB*EMB, bv, pv, bpar, epar);

    flash_hmma<<<dim3(SEQ/64, NHEAD, BATCH), 128>>>(pq, pk, pv, oh, ol);

    gemm_bf16<false><<<ggrid, gblk, GEMM_SMEM>>>(oh, ol, wh + 3*EMB*EMB, wl + 3*EMB*EMB, bo, (float*)d_out, bpar, epar);
}